// round 2
// baseline (speedup 1.0000x reference)
#include <cuda_runtime.h>
#include <cstdint>

#define N_NODES 50000
#define FDIM    64
#define PER     8
#define E_EDGES 800000
#define NF      (N_NODES * FDIM)   // 3,200,000

// ---------------- scratch (static __device__ — no allocations) ----------------
__device__ float g_Xt[PER * NF];        // X transposed: [p][n][f]  (~102 MB)
__device__ float g_tx1[NF];             // L_hat @ Xp for current period
__device__ float g_deg[N_NODES];
__device__ int   g_cnt[N_NODES];
__device__ int   g_rowptr[N_NODES + 1];
__device__ int   g_cursor[N_NODES];
__device__ int   g_esrc[E_EDGES];
__device__ float g_ewn[E_EDGES];
__device__ float g_Wc[128 * 192];       // packed [k][j], j = f*3 + g (g: i,c,o)
__device__ float g_bs[192];             // bx+bh+bg packed same j layout
__device__ float g_wo[64];              // peephole wc[2]

// ---------------- activations ----------------
__device__ __forceinline__ float fsigmoid(float x) {
    return __fdividef(1.0f, 1.0f + __expf(-x));
}
__device__ __forceinline__ float ftanh(float x) {
    x = fminf(fmaxf(x, -15.0f), 15.0f);
    float e = __expf(2.0f * x);
    return __fdividef(e - 1.0f, e + 1.0f);
}

// ---------------- setup kernels ----------------
__global__ void zero_kernel(float* __restrict__ out) {
    int t = blockIdx.x * blockDim.x + threadIdx.x;
    if (t < NF) out[t] = 0.0f;
    if (t < N_NODES) { g_deg[t] = 0.0f; g_cnt[t] = 0; }
}

// X: [N, F, P] -> g_Xt[p][n*64+f]
__global__ void transpose_kernel(const float* __restrict__ X) {
    int t = blockIdx.x * blockDim.x + threadIdx.x;
    if (t >= NF) return;
    const float4* src = reinterpret_cast<const float4*>(X + (size_t)t * 8);
    float4 a = src[0], b = src[1];
    float v[8] = {a.x, a.y, a.z, a.w, b.x, b.y, b.z, b.w};
#pragma unroll
    for (int p = 0; p < PER; p++) g_Xt[p * NF + t] = v[p];
}

__global__ void pack_w_kernel(const float* __restrict__ Wx0, const float* __restrict__ Wx1) {
    int idx = blockIdx.x * blockDim.x + threadIdx.x;
    if (idx >= 128 * 192) return;
    int k = idx / 192, j = idx % 192;
    int f = j / 3, g3 = j % 3;
    int gg = (g3 == 0) ? 0 : ((g3 == 1) ? 2 : 3);   // i, c, o -> orig gate idx
    float v = (k < 64) ? Wx0[gg * 4096 + k * 64 + f]
                       : Wx1[gg * 4096 + (k - 64) * 64 + f];
    g_Wc[idx] = v;
}

__global__ void pack_b_kernel(const float* __restrict__ bx, const float* __restrict__ bh,
                              const float* __restrict__ bg, const float* __restrict__ wc) {
    int j = threadIdx.x;           // 192 threads
    if (j < 192) {
        int f = j / 3, g3 = j % 3;
        int gg = (g3 == 0) ? 0 : ((g3 == 1) ? 2 : 3);
        g_bs[j] = bx[gg * 64 + f] + bh[gg * 64 + f] + bg[gg * 64 + f];
    }
    if (j < 64) g_wo[j] = wc[2 * 64 + j];
}

// degree (segment over src) + histogram of dst (for CSR)
__global__ void deg_hist_kernel(const int* __restrict__ ei, const float* __restrict__ ew) {
    int e = blockIdx.x * blockDim.x + threadIdx.x;
    if (e >= E_EDGES) return;
    atomicAdd(&g_deg[ei[e]], ew[e]);
    atomicAdd(&g_cnt[ei[E_EDGES + e]], 1);
}

// single-block exclusive scan of g_cnt -> g_rowptr, g_cursor
__global__ void scan_kernel() {
    __shared__ int wsum[32];
    __shared__ int carry_s;
    __shared__ int chunktotal;
    int tid = threadIdx.x;
    int lane = tid & 31, wid = tid >> 5;
    if (tid == 0) carry_s = 0;
    __syncthreads();
    for (int base = 0; base < N_NODES; base += 1024) {
        int i = base + tid;
        int v = (i < N_NODES) ? g_cnt[i] : 0;
        int x = v;
#pragma unroll
        for (int off = 1; off < 32; off <<= 1) {
            int t = __shfl_up_sync(0xffffffffu, x, off);
            if (lane >= off) x += t;
        }
        if (lane == 31) wsum[wid] = x;
        __syncthreads();
        if (wid == 0) {
            int s = wsum[lane];
            int y = s;
#pragma unroll
            for (int off = 1; off < 32; off <<= 1) {
                int t = __shfl_up_sync(0xffffffffu, y, off);
                if (lane >= off) y += t;
            }
            wsum[lane] = y - s;          // exclusive warp offset
            if (lane == 31) chunktotal = y;
        }
        __syncthreads();
        int incl = x + wsum[wid];
        int excl = carry_s + incl - v;
        if (i < N_NODES) { g_rowptr[i] = excl; g_cursor[i] = excl; }
        __syncthreads();
        if (tid == 0) carry_s += chunktotal;
        __syncthreads();
    }
    if (tid == 0) g_rowptr[N_NODES] = carry_s;
}

// normalized edge weight + scatter edges into CSR buckets keyed by dst
__global__ void wn_scatter_kernel(const int* __restrict__ ei, const float* __restrict__ ew) {
    int e = blockIdx.x * blockDim.x + threadIdx.x;
    if (e >= E_EDGES) return;
    int s = ei[e], d = ei[E_EDGES + e];
    float ds = g_deg[s], dd = g_deg[d];
    float is = (ds > 0.0f) ? rsqrtf(fmaxf(ds, 1e-12f)) : 0.0f;
    float id = (dd > 0.0f) ? rsqrtf(fmaxf(dd, 1e-12f)) : 0.0f;
    float w = -is * ew[e] * id;
    int pos = atomicAdd(&g_cursor[d], 1);
    g_esrc[pos] = s;
    g_ewn[pos] = w;
}

// ---------------- pull SpMM: tx1[n] = sum_{e in CSR[n]} wn_e * Xp[src_e] ----------------
__global__ void __launch_bounds__(256) spmm_kernel(int p) {
    const float* __restrict__ Xp = g_Xt + p * NF;
    int warp = (blockIdx.x * blockDim.x + threadIdx.x) >> 5;
    int lane = threadIdx.x & 31;
    if (warp >= N_NODES) return;
    int beg = g_rowptr[warp], end = g_rowptr[warp + 1];
    int f = lane * 2;
    float ax = 0.0f, ay = 0.0f;
    int e = beg;
    for (; e + 1 < end; e += 2) {
        int s0 = g_esrc[e], s1 = g_esrc[e + 1];
        float w0 = g_ewn[e], w1 = g_ewn[e + 1];
        float2 x0 = *reinterpret_cast<const float2*>(Xp + (size_t)s0 * 64 + f);
        float2 x1 = *reinterpret_cast<const float2*>(Xp + (size_t)s1 * 64 + f);
        ax += w0 * x0.x + w1 * x1.x;
        ay += w0 * x0.y + w1 * x1.y;
    }
    if (e < end) {
        int s0 = g_esrc[e];
        float w0 = g_ewn[e];
        float2 x0 = *reinterpret_cast<const float2*>(Xp + (size_t)s0 * 64 + f);
        ax += w0 * x0.x;
        ay += w0 * x0.y;
    }
    *reinterpret_cast<float2*>(g_tx1 + (size_t)warp * 64 + f) = make_float2(ax, ay);
}

// ---------------- fused GEMM + LSTM epilogue ----------------
// A = [Xp | tx1] (Nx128), W = g_Wc (128x192, j=f*3+g), out += O*tanh(Cn)
#define AS_STRIDE 68
#define GEMM_SMEM ((128 * AS_STRIDE + 128 * 192) * 4)

__global__ void __launch_bounds__(256, 1) gemm_fused_kernel(int p, float* __restrict__ out) {
    extern __shared__ float smem[];
    float* As = smem;                       // [k=128][row=64] stride 68
    float* Ws = smem + 128 * AS_STRIDE;     // [k=128][j=192]
    const float* __restrict__ Xp = g_Xt + p * NF;

    int r0 = blockIdx.x * 64;
    int tid = threadIdx.x;

    // load W tile (24576 floats)
#pragma unroll
    for (int i = tid; i < 6144; i += 256)
        reinterpret_cast<float4*>(Ws)[i] = reinterpret_cast<const float4*>(g_Wc)[i];

    // load A tile transposed: As[k][row]
#pragma unroll
    for (int half = 0; half < 2; half++) {
        const float* src = half ? g_tx1 : Xp;
#pragma unroll
        for (int it = 0; it < 4; it++) {
            int i4 = tid + it * 256;        // 0..1023
            int row = i4 >> 4;              // 0..63
            int f4 = i4 & 15;               // 0..15
            float4 v = make_float4(0.f, 0.f, 0.f, 0.f);
            int gr = r0 + row;
            if (gr < N_NODES)
                v = *reinterpret_cast<const float4*>(src + (size_t)gr * 64 + f4 * 4);
            int kb = half * 64 + f4 * 4;
            As[(kb + 0) * AS_STRIDE + row] = v.x;
            As[(kb + 1) * AS_STRIDE + row] = v.y;
            As[(kb + 2) * AS_STRIDE + row] = v.z;
            As[(kb + 3) * AS_STRIDE + row] = v.w;
        }
    }
    __syncthreads();

    int tc = tid & 15;     // 16 col-groups of 12 (= 4 f x 3 gates)
    int tr = tid >> 4;     // 16 row-groups of 4
    float acc[4][12];
#pragma unroll
    for (int r = 0; r < 4; r++)
#pragma unroll
        for (int c = 0; c < 12; c++) acc[r][c] = 0.0f;

    const float* ap = As + tr * 4;
    const float* wp = Ws + tc * 12;

#pragma unroll 8
    for (int k = 0; k < 128; k++) {
        float4 a  = *reinterpret_cast<const float4*>(ap + k * AS_STRIDE);
        float4 b0 = *reinterpret_cast<const float4*>(wp + k * 192);
        float4 b1 = *reinterpret_cast<const float4*>(wp + k * 192 + 4);
        float4 b2 = *reinterpret_cast<const float4*>(wp + k * 192 + 8);
        float av[4] = {a.x, a.y, a.z, a.w};
        float bv[12] = {b0.x, b0.y, b0.z, b0.w, b1.x, b1.y, b1.z, b1.w,
                        b2.x, b2.y, b2.z, b2.w};
#pragma unroll
        for (int r = 0; r < 4; r++)
#pragma unroll
            for (int c = 0; c < 12; c++) acc[r][c] += av[r] * bv[c];
    }

    // epilogue: thread owns f = tc*4 + u (u=0..3), gates i,c,o interleaved
    float bs[12];
#pragma unroll
    for (int c = 0; c < 12; c++) bs[c] = g_bs[tc * 12 + c];
    float wo[4];
#pragma unroll
    for (int u = 0; u < 4; u++) wo[u] = g_wo[tc * 4 + u];

#pragma unroll
    for (int r = 0; r < 4; r++) {
        int row = r0 + tr * 4 + r;
        if (row >= N_NODES) break;
        float4* op = reinterpret_cast<float4*>(out + (size_t)row * 64 + tc * 4);
        float4 o = *op;
        float res[4];
#pragma unroll
        for (int u = 0; u < 4; u++) {
            float gi = acc[r][u * 3 + 0] + bs[u * 3 + 0];
            float gc = acc[r][u * 3 + 1] + bs[u * 3 + 1];
            float go = acc[r][u * 3 + 2] + bs[u * 3 + 2];
            float I  = fsigmoid(gi);
            float T  = ftanh(gc);
            float Cn = I * T;
            float O  = fsigmoid(go + wo[u] * Cn);
            res[u] = O * ftanh(Cn);
        }
        o.x += res[0]; o.y += res[1]; o.z += res[2]; o.w += res[3];
        *op = o;
    }
}

// ---------------- launch ----------------
extern "C" void kernel_launch(void* const* d_in, const int* in_sizes, int n_in,
                              void* d_out, int out_size) {
    const float* X   = (const float*)d_in[0];
    const int*   ei  = (const int*)d_in[1];
    const float* ew  = (const float*)d_in[2];
    const float* Wx0 = (const float*)d_in[3];
    const float* Wx1 = (const float*)d_in[4];
    const float* bx  = (const float*)d_in[5];
    // d_in[6] = Wh0, d_in[7] = Wh1 : unused (H=0 -> cheb(H)=bh)
    const float* bh  = (const float*)d_in[8];
    const float* wc  = (const float*)d_in[9];
    const float* bg  = (const float*)d_in[10];
    float* out = (float*)d_out;

    cudaFuncSetAttribute(gemm_fused_kernel,
                         cudaFuncAttributeMaxDynamicSharedMemorySize, GEMM_SMEM);

    zero_kernel<<<(NF + 255) / 256, 256>>>(out);
    transpose_kernel<<<(NF + 255) / 256, 256>>>(X);
    pack_w_kernel<<<(128 * 192 + 255) / 256, 256>>>(Wx0, Wx1);
    pack_b_kernel<<<1, 192>>>(bx, bh, bg, wc);
    deg_hist_kernel<<<(E_EDGES + 255) / 256, 256>>>(ei, ew);
    scan_kernel<<<1, 1024>>>();
    wn_scatter_kernel<<<(E_EDGES + 255) / 256, 256>>>(ei, ew);

    int spmm_blocks = (N_NODES * 32 + 255) / 256;       // warp per node
    int gemm_blocks = (N_NODES + 63) / 64;
    for (int p = 0; p < PER; p++) {
        spmm_kernel<<<spmm_blocks, 256>>>(p);
        gemm_fused_kernel<<<gemm_blocks, 256, GEMM_SMEM>>>(p, out);
    }
}

// round 5
// speedup vs baseline: 1.5395x; 1.5395x over previous
#include <cuda_runtime.h>
#include <cuda_bf16.h>
#include <cstdint>

#define N_NODES 50000
#define FDIM    64
#define PER     8
#define E_EDGES 800000
#define NF      (N_NODES * FDIM)

// ---------------- scratch (static __device__ — no allocations) ----------------
// Interleaved bf16 hi/lo pairs: per node row, 32 uint2; u.x = hi(f0)|hi(f1)<<16, u.y = lo pair
__device__ uint2 g_XI[PER * N_NODES * 32];   // X transposed+split  (~102 MB)
__device__ uint2 g_TI[PER * N_NODES * 32];   // tx1 per period, split
__device__ float g_deg[N_NODES];
__device__ int   g_cnt[N_NODES];
__device__ int   g_rowptr[N_NODES + 1];
__device__ int   g_cursor[N_NODES];
__device__ int   g_esrc[E_EDGES];
__device__ float g_ewn[E_EDGES];
__device__ unsigned short g_Wbh[192 * 128];  // W packed [j][k], j=f*3+{i,c,o}, bf16 hi
__device__ unsigned short g_Wbl[192 * 128];  // bf16 lo
__device__ float g_bs[192];                  // bx+bh+bg, j layout
__device__ float g_wo[64];                   // peephole wc[2]

// ---------------- small helpers ----------------
__device__ __forceinline__ unsigned f2bf(float x) {
    unsigned short r; asm("cvt.rn.bf16.f32 %0, %1;" : "=h"(r) : "f"(x));
    return (unsigned)r;
}
__device__ __forceinline__ float fsigmoid(float x) {
    return __fdividef(1.0f, 1.0f + __expf(-x));
}
__device__ __forceinline__ float ftanh(float x) {
    x = fminf(fmaxf(x, -15.0f), 15.0f);
    float e = __expf(2.0f * x);
    return __fdividef(e - 1.0f, e + 1.0f);
}

// mma.sync m16n8k16 bf16 (sm_80+ baseline PTX — valid on plain sm_103)
__device__ __forceinline__ void mma_bf16(float* c,
                                         uint32_t a0, uint32_t a1, uint32_t a2, uint32_t a3,
                                         uint32_t b0, uint32_t b1) {
    asm volatile(
        "mma.sync.aligned.m16n8k16.row.col.f32.bf16.bf16.f32 "
        "{%0,%1,%2,%3}, {%4,%5,%6,%7}, {%8,%9}, {%0,%1,%2,%3};"
        : "+f"(c[0]), "+f"(c[1]), "+f"(c[2]), "+f"(c[3])
        : "r"(a0), "r"(a1), "r"(a2), "r"(a3), "r"(b0), "r"(b1));
}

// ---------------- setup kernels ----------------
__global__ void zero_kernel() {
    int t = blockIdx.x * blockDim.x + threadIdx.x;
    if (t < N_NODES) { g_deg[t] = 0.0f; g_cnt[t] = 0; }
}

// X: [N, F, P] fp32 -> g_XI[p][n][pair] interleaved bf16 hi/lo
__global__ void transpose_kernel(const float* __restrict__ X) {
    int t = blockIdx.x * blockDim.x + threadIdx.x;
    if (t >= NF / 2) return;
    int n = t >> 5, j = t & 31;
    const float4* src = reinterpret_cast<const float4*>(X + ((size_t)n * 64 + 2 * j) * 8);
    float4 v0 = src[0], v1 = src[1], v2 = src[2], v3 = src[3];
    float f0[8] = {v0.x, v0.y, v0.z, v0.w, v1.x, v1.y, v1.z, v1.w};
    float f1[8] = {v2.x, v2.y, v2.z, v2.w, v3.x, v3.y, v3.z, v3.w};
#pragma unroll
    for (int p = 0; p < PER; p++) {
        unsigned h0 = f2bf(f0[p]);
        unsigned l0 = f2bf(f0[p] - __uint_as_float(h0 << 16));
        unsigned h1 = f2bf(f1[p]);
        unsigned l1 = f2bf(f1[p] - __uint_as_float(h1 << 16));
        uint2 u; u.x = h0 | (h1 << 16); u.y = l0 | (l1 << 16);
        g_XI[((size_t)p * N_NODES + n) * 32 + j] = u;
    }
}

__global__ void pack_w_kernel(const float* __restrict__ Wx0, const float* __restrict__ Wx1) {
    int idx = blockIdx.x * blockDim.x + threadIdx.x;
    if (idx >= 192 * 128) return;
    int j = idx >> 7, k = idx & 127;
    int f = j / 3, g3 = j % 3;
    int gg = (g3 == 0) ? 0 : ((g3 == 1) ? 2 : 3);   // i, c, o
    float v = (k < 64) ? Wx0[gg * 4096 + k * 64 + f]
                       : Wx1[gg * 4096 + (k - 64) * 64 + f];
    unsigned h = f2bf(v);
    unsigned l = f2bf(v - __uint_as_float(h << 16));
    g_Wbh[idx] = (unsigned short)h;
    g_Wbl[idx] = (unsigned short)l;
}

__global__ void pack_b_kernel(const float* __restrict__ bx, const float* __restrict__ bh,
                              const float* __restrict__ bg, const float* __restrict__ wc) {
    int j = threadIdx.x;
    if (j < 192) {
        int f = j / 3, g3 = j % 3;
        int gg = (g3 == 0) ? 0 : ((g3 == 1) ? 2 : 3);
        g_bs[j] = bx[gg * 64 + f] + bh[gg * 64 + f] + bg[gg * 64 + f];
    }
    if (j < 64) g_wo[j] = wc[2 * 64 + j];
}

__global__ void deg_hist_kernel(const int* __restrict__ ei, const float* __restrict__ ew) {
    int e = blockIdx.x * blockDim.x + threadIdx.x;
    if (e >= E_EDGES) return;
    atomicAdd(&g_deg[ei[e]], ew[e]);
    atomicAdd(&g_cnt[ei[E_EDGES + e]], 1);
}

__global__ void scan_kernel() {
    __shared__ int wsum[32];
    __shared__ int carry_s;
    __shared__ int chunktotal;
    int tid = threadIdx.x;
    int lane = tid & 31, wid = tid >> 5;
    if (tid == 0) carry_s = 0;
    __syncthreads();
    for (int base = 0; base < N_NODES; base += 1024) {
        int i = base + tid;
        int v = (i < N_NODES) ? g_cnt[i] : 0;
        int x = v;
#pragma unroll
        for (int off = 1; off < 32; off <<= 1) {
            int t = __shfl_up_sync(0xffffffffu, x, off);
            if (lane >= off) x += t;
        }
        if (lane == 31) wsum[wid] = x;
        __syncthreads();
        if (wid == 0) {
            int s = wsum[lane];
            int y = s;
#pragma unroll
            for (int off = 1; off < 32; off <<= 1) {
                int t = __shfl_up_sync(0xffffffffu, y, off);
                if (lane >= off) y += t;
            }
            wsum[lane] = y - s;
            if (lane == 31) chunktotal = y;
        }
        __syncthreads();
        int incl = x + wsum[wid];
        int excl = carry_s + incl - v;
        if (i < N_NODES) { g_rowptr[i] = excl; g_cursor[i] = excl; }
        __syncthreads();
        if (tid == 0) carry_s += chunktotal;
        __syncthreads();
    }
    if (tid == 0) g_rowptr[N_NODES] = carry_s;
}

__global__ void wn_scatter_kernel(const int* __restrict__ ei, const float* __restrict__ ew) {
    int e = blockIdx.x * blockDim.x + threadIdx.x;
    if (e >= E_EDGES) return;
    int s = ei[e], d = ei[E_EDGES + e];
    float ds = g_deg[s], dd = g_deg[d];
    float is = (ds > 0.0f) ? rsqrtf(fmaxf(ds, 1e-12f)) : 0.0f;
    float id = (dd > 0.0f) ? rsqrtf(fmaxf(dd, 1e-12f)) : 0.0f;
    float w = -is * ew[e] * id;
    int pos = atomicAdd(&g_cursor[d], 1);
    g_esrc[pos] = s;
    g_ewn[pos] = w;
}

// ---------------- pull SpMM (bf16 hi/lo source, split bf16 output) ----------------
__global__ void __launch_bounds__(256) spmm_kernel(int p) {
    const uint2* __restrict__ Xp = g_XI + (size_t)p * N_NODES * 32;
    int warp = (blockIdx.x * blockDim.x + threadIdx.x) >> 5;
    int lane = threadIdx.x & 31;
    if (warp >= N_NODES) return;
    int beg = g_rowptr[warp], end = g_rowptr[warp + 1];
    float ax = 0.0f, ay = 0.0f;
    int e = beg;
    for (; e + 1 < end; e += 2) {
        int s0 = g_esrc[e], s1 = g_esrc[e + 1];
        float w0 = g_ewn[e], w1 = g_ewn[e + 1];
        uint2 u0 = Xp[(size_t)s0 * 32 + lane];
        uint2 u1 = Xp[(size_t)s1 * 32 + lane];
        float x00 = __uint_as_float(u0.x << 16) + __uint_as_float(u0.y << 16);
        float x01 = __uint_as_float(u0.x & 0xFFFF0000u) + __uint_as_float(u0.y & 0xFFFF0000u);
        float x10 = __uint_as_float(u1.x << 16) + __uint_as_float(u1.y << 16);
        float x11 = __uint_as_float(u1.x & 0xFFFF0000u) + __uint_as_float(u1.y & 0xFFFF0000u);
        ax += w0 * x00 + w1 * x10;
        ay += w0 * x01 + w1 * x11;
    }
    if (e < end) {
        int s0 = g_esrc[e];
        float w0 = g_ewn[e];
        uint2 u0 = Xp[(size_t)s0 * 32 + lane];
        float x00 = __uint_as_float(u0.x << 16) + __uint_as_float(u0.y << 16);
        float x01 = __uint_as_float(u0.x & 0xFFFF0000u) + __uint_as_float(u0.y & 0xFFFF0000u);
        ax += w0 * x00;
        ay += w0 * x01;
    }
    unsigned hx = f2bf(ax);
    unsigned lx = f2bf(ax - __uint_as_float(hx << 16));
    unsigned hy = f2bf(ay);
    unsigned ly = f2bf(ay - __uint_as_float(hy << 16));
    uint2 o; o.x = hx | (hy << 16); o.y = lx | (ly << 16);
    g_TI[((size_t)p * N_NODES + warp) * 32 + lane] = o;
}

// ---------------- fused mma.sync GEMM: all 8 periods per block ----------------
// smem layout (bytes from dynamic-smem base; base is >=128B aligned):
//   A: [row 128][k 128] bf16, row stride 272B, hi plane then lo plane (2x34816)
//   D buffer (fp32, 128 x 100 floats = 51200 B) ALIASES the A region (A dead post-mma)
//   B: [j 192][k 128] bf16, row stride 272B, hi + lo planes (2x52224)
#define ASTRIDE 272
#define APL     34816
#define BSTRIDE 272
#define BPL     52224
#define DSTRIDE 100           // floats
#define SM_A    0
#define SM_D    0
#define SM_B    69632
#define SM_BS   174080
#define SM_WO   174848
#define SMEM_BYTES 175104

__global__ void __launch_bounds__(256, 1) gemm_fused(float* __restrict__ out) {
    extern __shared__ char smem[];
    int tid = threadIdx.x;
    int wid = tid >> 5, lane = tid & 31;
    int g = lane >> 2, tg = lane & 3;
    int wm = wid & 1;          // warp row: 0/1 -> rows 0-63 / 64-127
    int wn = wid >> 1;         // warp col: 0..3 -> cols 48*wn
    int r0 = blockIdx.x * 128;

    // ---- B copy (once): [192][128] bf16 hi+lo into padded rows ----
    for (int it = tid; it < 3072; it += 256) {
        int j = it >> 4, c = it & 15;
        *(uint4*)(smem + SM_B + j * BSTRIDE + c * 16) =
            *((const uint4*)g_Wbh + j * 16 + c);
        *(uint4*)(smem + SM_B + BPL + j * BSTRIDE + c * 16) =
            *((const uint4*)g_Wbl + j * 16 + c);
    }
    if (tid < 192) ((float*)(smem + SM_BS))[tid] = g_bs[tid];
    if (tid < 64)  ((float*)(smem + SM_WO))[tid] = g_wo[tid];

    float accO[32];
#pragma unroll
    for (int i = 0; i < 32; i++) accO[i] = 0.0f;
    int row_e = tid >> 1;            // epilogue row owned by this thread
    int flb = (tid & 1) * 16;        // epilogue f-local base

    for (int p = 0; p < PER; p++) {
        __syncthreads();   // prior epilogue reads of D(=A region) done; B ready (p=0)

        // ---- A copy: 128 rows x 128 k from interleaved hi/lo sources ----
        {
            const uint4* XI = (const uint4*)(g_XI + (size_t)p * N_NODES * 32);
            const uint4* TI = (const uint4*)(g_TI + (size_t)p * N_NODES * 32);
#pragma unroll
            for (int it4 = 0; it4 < 16; it4++) {
                int it = tid + it4 * 256;
                int c = it & 15, half = (it >> 4) & 1, r = it >> 5;
                int gr = r0 + r;
                uint4 u = make_uint4(0, 0, 0, 0);
                if (gr < N_NODES) u = (half ? TI : XI)[(size_t)gr * 16 + c];
                char* dst = smem + SM_A + r * ASTRIDE + half * 128 + c * 8;
                *(uint2*)dst         = make_uint2(u.x, u.z);   // hi plane
                *(uint2*)(dst + APL) = make_uint2(u.y, u.w);   // lo plane
            }
        }
        __syncthreads();

        // ---- mma: acc[mt][nt][q], 3-pass hi/lo ----
        float acc[4][6][4];
#pragma unroll
        for (int mt = 0; mt < 4; mt++)
#pragma unroll
            for (int nt = 0; nt < 6; nt++)
#pragma unroll
                for (int q = 0; q < 4; q++) acc[mt][nt][q] = 0.0f;

#pragma unroll
        for (int ks = 0; ks < 8; ks++) {
            uint32_t ah[4][4], al[4][4];
#pragma unroll
            for (int mt = 0; mt < 4; mt++) {
                const char* ab = smem + SM_A + (wm * 64 + mt * 16 + g) * ASTRIDE
                               + ks * 32 + tg * 4;
                ah[mt][0] = *(const uint32_t*)(ab);
                ah[mt][1] = *(const uint32_t*)(ab + 8 * ASTRIDE);
                ah[mt][2] = *(const uint32_t*)(ab + 16);
                ah[mt][3] = *(const uint32_t*)(ab + 8 * ASTRIDE + 16);
                al[mt][0] = *(const uint32_t*)(ab + APL);
                al[mt][1] = *(const uint32_t*)(ab + APL + 8 * ASTRIDE);
                al[mt][2] = *(const uint32_t*)(ab + APL + 16);
                al[mt][3] = *(const uint32_t*)(ab + APL + 8 * ASTRIDE + 16);
            }
#pragma unroll
            for (int nt = 0; nt < 6; nt++) {
                const char* bb = smem + SM_B + (wn * 48 + nt * 8 + g) * BSTRIDE
                               + ks * 32 + tg * 4;
                uint32_t bh0 = *(const uint32_t*)(bb);
                uint32_t bh1 = *(const uint32_t*)(bb + 16);
                uint32_t bl0 = *(const uint32_t*)(bb + BPL);
                uint32_t bl1 = *(const uint32_t*)(bb + BPL + 16);
#pragma unroll
                for (int mt = 0; mt < 4; mt++) {
                    mma_bf16(acc[mt][nt], ah[mt][0], ah[mt][1], ah[mt][2], ah[mt][3], bh0, bh1);
                    mma_bf16(acc[mt][nt], ah[mt][0], ah[mt][1], ah[mt][2], ah[mt][3], bl0, bl1);
                    mma_bf16(acc[mt][nt], al[mt][0], al[mt][1], al[mt][2], al[mt][3], bh0, bh1);
                }
            }
        }

        // ---- two 96-col phases: stage D in smem, run LSTM epilogue ----
#pragma unroll
        for (int h = 0; h < 2; h++) {
            __syncthreads();   // h=0: all mma A-reads done; h=1: phase-0 D reads done
            if ((wn >> 1) == h) {
                int cb = (wn & 1) * 48;
#pragma unroll
                for (int mt = 0; mt < 4; mt++) {
                    int r = wm * 64 + mt * 16 + g;
#pragma unroll
                    for (int nt = 0; nt < 6; nt++) {
                        float* dp = (float*)(smem + SM_D) + r * DSTRIDE + cb + nt * 8 + tg * 2;
                        *(float2*)dp = make_float2(acc[mt][nt][0], acc[mt][nt][1]);
                        *(float2*)(dp + 8 * DSTRIDE) = make_float2(acc[mt][nt][2], acc[mt][nt][3]);
                    }
                }
            }
            __syncthreads();
            const float* dr  = (const float*)(smem + SM_D) + row_e * DSTRIDE;
            const float* bsS = (const float*)(smem + SM_BS) + h * 96;
            const float* woS = (const float*)(smem + SM_WO) + h * 32;
#pragma unroll
            for (int i = 0; i < 16; i++) {
                int fl = flb + i;
                float gi = dr[fl * 3]     + bsS[fl * 3];
                float gc = dr[fl * 3 + 1] + bsS[fl * 3 + 1];
                float go = dr[fl * 3 + 2] + bsS[fl * 3 + 2];
                float I  = fsigmoid(gi);
                float T  = ftanh(gc);
                float Cn = I * T;
                float O  = fsigmoid(go + woS[fl] * Cn);
                accO[h * 16 + i] += O * ftanh(Cn);
            }
        }
    }

    // ---- final output write (only write to out; no RMW) ----
    int grow = r0 + row_e;
    if (grow < N_NODES) {
        float* op = out + (size_t)grow * 64;
#pragma unroll
        for (int q = 0; q < 4; q++)
            *(float4*)(op + flb + q * 4) =
                make_float4(accO[4 * q], accO[4 * q + 1], accO[4 * q + 2], accO[4 * q + 3]);
#pragma unroll
        for (int q = 0; q < 4; q++)
            *(float4*)(op + 32 + flb + q * 4) =
                make_float4(accO[16 + 4 * q], accO[17 + 4 * q], accO[18 + 4 * q], accO[19 + 4 * q]);
    }
}

// ---------------- launch ----------------
extern "C" void kernel_launch(void* const* d_in, const int* in_sizes, int n_in,
                              void* d_out, int out_size) {
    const float* X   = (const float*)d_in[0];
    const int*   ei  = (const int*)d_in[1];
    const float* ew  = (const float*)d_in[2];
    const float* Wx0 = (const float*)d_in[3];
    const float* Wx1 = (const float*)d_in[4];
    const float* bx  = (const float*)d_in[5];
    // d_in[6]=Wh0, d_in[7]=Wh1 unused (H=0 -> cheb(H)=bh)
    const float* bh  = (const float*)d_in[8];
    const float* wc  = (const float*)d_in[9];
    const float* bg  = (const float*)d_in[10];
    float* out = (float*)d_out;

    cudaFuncSetAttribute(gemm_fused, cudaFuncAttributeMaxDynamicSharedMemorySize, SMEM_BYTES);

    zero_kernel<<<(N_NODES + 255) / 256, 256>>>();
    transpose_kernel<<<(NF / 2 + 255) / 256, 256>>>(X);
    pack_w_kernel<<<(192 * 128 + 255) / 256, 256>>>(Wx0, Wx1);
    pack_b_kernel<<<1, 192>>>(bx, bh, bg, wc);
    deg_hist_kernel<<<(E_EDGES + 255) / 256, 256>>>(ei, ew);
    scan_kernel<<<1, 1024>>>();
    wn_scatter_kernel<<<(E_EDGES + 255) / 256, 256>>>(ei, ew);

    int spmm_blocks = (N_NODES * 32 + 255) / 256;
    for (int p = 0; p < PER; p++)
        spmm_kernel<<<spmm_blocks, 256>>>(p);

    gemm_fused<<<(N_NODES + 127) / 128, 256, SMEM_BYTES>>>(out);
}

// round 7
// speedup vs baseline: 1.6478x; 1.0704x over previous
#include <cuda_runtime.h>
#include <cuda_bf16.h>
#include <cstdint>

#define N_NODES 50000
#define FDIM    64
#define PER     8
#define E_EDGES 800000
#define NF      (N_NODES * FDIM)

// ---------------- scratch (static __device__ — no allocations) ----------------
// Interleaved bf16 hi/lo pairs: per node row, 32 uint2; u.x = hi(f0)|hi(f1)<<16, u.y = lo pair
__device__ uint2 g_XI[PER * N_NODES * 32];   // X transposed+split  (~102 MB)
__device__ uint2 g_TI[PER * N_NODES * 32];   // tx1 per period, split
__device__ float g_deg[N_NODES];
__device__ int   g_cnt[N_NODES];
__device__ int   g_rowptr[N_NODES + 1];
__device__ int   g_cursor[N_NODES];
__device__ int   g_esrc[E_EDGES];
__device__ float g_ewn[E_EDGES];
__device__ unsigned short g_Wbh[192 * 128];  // W packed [jphys][k], bf16 hi (permuted cols)
__device__ unsigned short g_Wbl[192 * 128];  // bf16 lo
__device__ float g_bs[192];                  // bx+bh+bg, jphys layout
__device__ float g_wo[64];                   // peephole wc[2], logical f

// ---------------- small helpers ----------------
__device__ __forceinline__ unsigned f2bf(float x) {
    unsigned short r; asm("cvt.rn.bf16.f32 %0, %1;" : "=h"(r) : "f"(x));
    return (unsigned)r;
}
__device__ __forceinline__ float fsigmoid(float x) {
    return __fdividef(1.0f, 1.0f + __expf(-x));
}
__device__ __forceinline__ float ftanh(float x) {
    x = fminf(fmaxf(x, -15.0f), 15.0f);
    float e = __expf(2.0f * x);
    return __fdividef(e - 1.0f, e + 1.0f);
}

// physical B column jphys -> logical (feature f, gate g3 in {0:i,1:c,2:o})
__device__ __forceinline__ void jmap(int jp, int& f, int& g3) {
    int wn = jp / 48, rem = jp % 48;
    int nt = rem >> 3, r8 = rem & 7, tg = r8 >> 1, e = r8 & 1;
    int slot = nt * 2 + e;
    f  = wn * 16 + tg * 4 + slot / 3;
    g3 = slot % 3;
}

// mma.sync m16n8k16 bf16 (sm_80+ baseline PTX — valid on plain sm_103)
__device__ __forceinline__ void mma_bf16(float* c,
                                         uint32_t a0, uint32_t a1, uint32_t a2, uint32_t a3,
                                         uint32_t b0, uint32_t b1) {
    asm volatile(
        "mma.sync.aligned.m16n8k16.row.col.f32.bf16.bf16.f32 "
        "{%0,%1,%2,%3}, {%4,%5,%6,%7}, {%8,%9}, {%0,%1,%2,%3};"
        : "+f"(c[0]), "+f"(c[1]), "+f"(c[2]), "+f"(c[3])
        : "r"(a0), "r"(a1), "r"(a2), "r"(a3), "r"(b0), "r"(b1));
}

// ---------------- setup: zero + pack_w + pack_b in ONE kernel ----------------
__global__ void setup_kernel(const float* __restrict__ Wx0, const float* __restrict__ Wx1,
                             const float* __restrict__ bx, const float* __restrict__ bh,
                             const float* __restrict__ bg, const float* __restrict__ wc) {
    int t = blockIdx.x * blockDim.x + threadIdx.x;
    if (t < N_NODES) { g_deg[t] = 0.0f; g_cnt[t] = 0; }
    if (t < 192 * 128) {
        int jp = t >> 7, k = t & 127;
        int f, g3; jmap(jp, f, g3);
        int gg = (g3 == 0) ? 0 : ((g3 == 1) ? 2 : 3);
        float v = (k < 64) ? Wx0[gg * 4096 + k * 64 + f]
                           : Wx1[gg * 4096 + (k - 64) * 64 + f];
        unsigned h = f2bf(v);
        unsigned l = f2bf(v - __uint_as_float(h << 16));
        g_Wbh[t] = (unsigned short)h;
        g_Wbl[t] = (unsigned short)l;
    }
    if (t < 192) {
        int f, g3; jmap(t, f, g3);
        int gg = (g3 == 0) ? 0 : ((g3 == 1) ? 2 : 3);
        g_bs[t] = bx[gg * 64 + f] + bh[gg * 64 + f] + bg[gg * 64 + f];
    }
    if (t < 64) g_wo[t] = wc[2 * 64 + t];
}

// X: [N, F, P] fp32 -> g_XI[p][n][pair] interleaved bf16 hi/lo
__global__ void transpose_kernel(const float* __restrict__ X) {
    int t = blockIdx.x * blockDim.x + threadIdx.x;
    if (t >= NF / 2) return;
    int n = t >> 5, j = t & 31;
    const float4* src = reinterpret_cast<const float4*>(X + ((size_t)n * 64 + 2 * j) * 8);
    float4 v0 = src[0], v1 = src[1], v2 = src[2], v3 = src[3];
    float f0[8] = {v0.x, v0.y, v0.z, v0.w, v1.x, v1.y, v1.z, v1.w};
    float f1[8] = {v2.x, v2.y, v2.z, v2.w, v3.x, v3.y, v3.z, v3.w};
#pragma unroll
    for (int p = 0; p < PER; p++) {
        unsigned h0 = f2bf(f0[p]);
        unsigned l0 = f2bf(f0[p] - __uint_as_float(h0 << 16));
        unsigned h1 = f2bf(f1[p]);
        unsigned l1 = f2bf(f1[p] - __uint_as_float(h1 << 16));
        uint2 u; u.x = h0 | (h1 << 16); u.y = l0 | (l1 << 16);
        g_XI[((size_t)p * N_NODES + n) * 32 + j] = u;
    }
}

__global__ void deg_hist_kernel(const int* __restrict__ ei, const float* __restrict__ ew) {
    int e = blockIdx.x * blockDim.x + threadIdx.x;
    if (e >= E_EDGES) return;
    atomicAdd(&g_deg[ei[e]], ew[e]);
    atomicAdd(&g_cnt[ei[E_EDGES + e]], 1);
}

__global__ void scan_kernel() {
    __shared__ int wsum[32];
    __shared__ int carry_s;
    __shared__ int chunktotal;
    int tid = threadIdx.x;
    int lane = tid & 31, wid = tid >> 5;
    if (tid == 0) carry_s = 0;
    __syncthreads();
    for (int base = 0; base < N_NODES; base += 1024) {
        int i = base + tid;
        int v = (i < N_NODES) ? g_cnt[i] : 0;
        int x = v;
#pragma unroll
        for (int off = 1; off < 32; off <<= 1) {
            int t = __shfl_up_sync(0xffffffffu, x, off);
            if (lane >= off) x += t;
        }
        if (lane == 31) wsum[wid] = x;
        __syncthreads();
        if (wid == 0) {
            int s = wsum[lane];
            int y = s;
#pragma unroll
            for (int off = 1; off < 32; off <<= 1) {
                int t = __shfl_up_sync(0xffffffffu, y, off);
                if (lane >= off) y += t;
            }
            wsum[lane] = y - s;
            if (lane == 31) chunktotal = y;
        }
        __syncthreads();
        int incl = x + wsum[wid];
        int excl = carry_s + incl - v;
        if (i < N_NODES) { g_rowptr[i] = excl; g_cursor[i] = excl; }
        __syncthreads();
        if (tid == 0) carry_s += chunktotal;
        __syncthreads();
    }
    if (tid == 0) g_rowptr[N_NODES] = carry_s;
}

__global__ void wn_scatter_kernel(const int* __restrict__ ei, const float* __restrict__ ew) {
    int e = blockIdx.x * blockDim.x + threadIdx.x;
    if (e >= E_EDGES) return;
    int s = ei[e], d = ei[E_EDGES + e];
    float ds = g_deg[s], dd = g_deg[d];
    float is = (ds > 0.0f) ? rsqrtf(fmaxf(ds, 1e-12f)) : 0.0f;
    float id = (dd > 0.0f) ? rsqrtf(fmaxf(dd, 1e-12f)) : 0.0f;
    float w = -is * ew[e] * id;
    int pos = atomicAdd(&g_cursor[d], 1);
    g_esrc[pos] = s;
    g_ewn[pos] = w;
}

// ---------------- pull SpMM, ALL periods in one launch (warp per node) ----------------
__global__ void __launch_bounds__(256) spmm_all_kernel() {
    int warp = (blockIdx.x * blockDim.x + threadIdx.x) >> 5;
    int lane = threadIdx.x & 31;
    if (warp >= N_NODES) return;
    int beg = g_rowptr[warp], end = g_rowptr[warp + 1];
    float ax[PER], ay[PER];
#pragma unroll
    for (int p = 0; p < PER; p++) { ax[p] = 0.0f; ay[p] = 0.0f; }
    for (int e = beg; e < end; e++) {
        int s = g_esrc[e];
        float w = g_ewn[e];
        const uint2* base = g_XI + (size_t)s * 32 + lane;
        uint2 u[PER];
#pragma unroll
        for (int p = 0; p < PER; p++) u[p] = base[(size_t)p * N_NODES * 32];
#pragma unroll
        for (int p = 0; p < PER; p++) {
            float x0 = __uint_as_float(u[p].x << 16) + __uint_as_float(u[p].y << 16);
            float x1 = __uint_as_float(u[p].x & 0xFFFF0000u) + __uint_as_float(u[p].y & 0xFFFF0000u);
            ax[p] += w * x0;
            ay[p] += w * x1;
        }
    }
#pragma unroll
    for (int p = 0; p < PER; p++) {
        unsigned hx = f2bf(ax[p]);
        unsigned lx = f2bf(ax[p] - __uint_as_float(hx << 16));
        unsigned hy = f2bf(ay[p]);
        unsigned ly = f2bf(ay[p] - __uint_as_float(hy << 16));
        uint2 o; o.x = hx | (hy << 16); o.y = lx | (ly << 16);
        g_TI[((size_t)p * N_NODES + warp) * 32 + lane] = o;
    }
}

// ---------------- fused mma.sync GEMM: all 8 periods per block ----------------
// smem: A [row 128][k 128] bf16 hi/lo planes (row stride 272B), B [jphys 192][k 128] hi/lo
#define ASTRIDE 272
#define APL     34816
#define BSTRIDE 272
#define BPL     52224
#define SM_A    0
#define SM_B    69632
#define SMEM_BYTES (69632 + 104448)

__global__ void __launch_bounds__(256, 1) gemm_fused(float* __restrict__ out) {
    extern __shared__ char smem[];
    int tid = threadIdx.x;
    int wid = tid >> 5, lane = tid & 31;
    int g = lane >> 2, tg = lane & 3;
    int wm = wid & 1;          // warp row: 0/1 -> rows 0-63 / 64-127
    int wn = wid >> 1;         // warp col: 0..3 -> jphys base 48*wn
    int r0 = blockIdx.x * 128;

    // ---- B copy (once) ----
    for (int it = tid; it < 3072; it += 256) {
        int j = it >> 4, c = it & 15;
        *(uint4*)(smem + SM_B + j * BSTRIDE + c * 16) = ((const uint4*)g_Wbh)[j * 16 + c];
        *(uint4*)(smem + SM_B + BPL + j * BSTRIDE + c * 16) = ((const uint4*)g_Wbl)[j * 16 + c];
    }

    // ---- per-thread biases (thread-local epilogue thanks to column permutation) ----
    float bsv[12], wov[4];
#pragma unroll
    for (int s = 0; s < 12; s++) {
        int nt = s >> 1, e = s & 1;
        bsv[s] = g_bs[wn * 48 + nt * 8 + tg * 2 + e];
    }
#pragma unroll
    for (int t = 0; t < 4; t++) wov[t] = g_wo[wn * 16 + tg * 4 + t];

    float accO[4][2][4];
#pragma unroll
    for (int mt = 0; mt < 4; mt++)
#pragma unroll
        for (int h = 0; h < 2; h++)
#pragma unroll
            for (int t = 0; t < 4; t++) accO[mt][h][t] = 0.0f;

    // copyA pieces: tid owns fixed (cc, half), rows (tid>>5) + it4*8
    int cc = tid & 15, half = (tid >> 4) & 1, rb = tid >> 5;
    char* dst0 = smem + SM_A + half * 128 + cc * 8;

    // ---- initial A copy (p = 0) ----
    {
        const uint4* XI = (const uint4*)(g_XI);
        const uint4* TI = (const uint4*)(g_TI);
        const uint4* srcp = half ? TI : XI;
#pragma unroll
        for (int it4 = 0; it4 < 16; it4++) {
            int r = rb + it4 * 8;
            int gr = r0 + r;
            uint4 u = make_uint4(0, 0, 0, 0);
            if (gr < N_NODES) u = srcp[(size_t)gr * 16 + cc];
            char* dst = dst0 + r * ASTRIDE;
            *(uint2*)dst         = make_uint2(u.x, u.z);
            *(uint2*)(dst + APL) = make_uint2(u.y, u.w);
        }
    }

    for (int p = 0; p < PER; p++) {
        __syncthreads();   // A(p) visible

        // ---- mma: acc[mt][nt][q], 3-pass bf16 hi/lo ----
        float acc[4][6][4];
#pragma unroll
        for (int mt = 0; mt < 4; mt++)
#pragma unroll
            for (int nt = 0; nt < 6; nt++)
#pragma unroll
                for (int q = 0; q < 4; q++) acc[mt][nt][q] = 0.0f;

#pragma unroll
        for (int ks = 0; ks < 8; ks++) {
            uint32_t ah[4][4], al[4][4];
#pragma unroll
            for (int mt = 0; mt < 4; mt++) {
                const char* ab = smem + SM_A + (wm * 64 + mt * 16 + g) * ASTRIDE
                               + ks * 32 + tg * 4;
                ah[mt][0] = *(const uint32_t*)(ab);
                ah[mt][1] = *(const uint32_t*)(ab + 8 * ASTRIDE);
                ah[mt][2] = *(const uint32_t*)(ab + 16);
                ah[mt][3] = *(const uint32_t*)(ab + 8 * ASTRIDE + 16);
                al[mt][0] = *(const uint32_t*)(ab + APL);
                al[mt][1] = *(const uint32_t*)(ab + APL + 8 * ASTRIDE);
                al[mt][2] = *(const uint32_t*)(ab + APL + 16);
                al[mt][3] = *(const uint32_t*)(ab + APL + 8 * ASTRIDE + 16);
            }
#pragma unroll
            for (int nt = 0; nt < 6; nt++) {
                const char* bb = smem + SM_B + (wn * 48 + nt * 8 + g) * BSTRIDE
                               + ks * 32 + tg * 4;
                uint32_t bh0 = *(const uint32_t*)(bb);
                uint32_t bh1 = *(const uint32_t*)(bb + 16);
                uint32_t bl0 = *(const uint32_t*)(bb + BPL);
                uint32_t bl1 = *(const uint32_t*)(bb + BPL + 16);
#pragma unroll
                for (int mt = 0; mt < 4; mt++) {
                    mma_bf16(acc[mt][nt], ah[mt][0], ah[mt][1], ah[mt][2], ah[mt][3], bh0, bh1);
                    mma_bf16(acc[mt][nt], ah[mt][0], ah[mt][1], ah[mt][2], ah[mt][3], bl0, bl1);
                    mma_bf16(acc[mt][nt], al[mt][0], al[mt][1], al[mt][2], al[mt][3], bh0, bh1);
                }
            }
        }
        __syncthreads();   // A reads done; safe to overwrite A

        // ---- thread-local epilogue + interleaved copyA(p+1) ----
        bool more = (p + 1 < PER);
        const uint4* srcp = nullptr;
        if (more) {
            const uint4* XI = (const uint4*)(g_XI + (size_t)(p + 1) * N_NODES * 32);
            const uint4* TI = (const uint4*)(g_TI + (size_t)(p + 1) * N_NODES * 32);
            srcp = half ? TI : XI;
        }
        uint4 u[8];
        if (more) {
#pragma unroll
            for (int i = 0; i < 8; i++) {
                int gr = r0 + rb + i * 8;
                u[i] = (gr < N_NODES) ? srcp[(size_t)gr * 16 + cc] : make_uint4(0, 0, 0, 0);
            }
        }
        // epilogue half 1 (mt 0..1)
#pragma unroll
        for (int mt = 0; mt < 2; mt++)
#pragma unroll
            for (int h = 0; h < 2; h++)
#pragma unroll
                for (int t = 0; t < 4; t++) {
                    int s0 = 3 * t, s1 = 3 * t + 1, s2 = 3 * t + 2;
                    float gi = acc[mt][s0 >> 1][h * 2 + (s0 & 1)] + bsv[s0];
                    float gc = acc[mt][s1 >> 1][h * 2 + (s1 & 1)] + bsv[s1];
                    float go = acc[mt][s2 >> 1][h * 2 + (s2 & 1)] + bsv[s2];
                    float I  = fsigmoid(gi);
                    float T  = ftanh(gc);
                    float Cn = I * T;
                    float O  = fsigmoid(go + wov[t] * Cn);
                    accO[mt][h][t] += O * ftanh(Cn);
                }
        if (more) {
#pragma unroll
            for (int i = 0; i < 8; i++) {
                char* dst = dst0 + (rb + i * 8) * ASTRIDE;
                *(uint2*)dst         = make_uint2(u[i].x, u[i].z);
                *(uint2*)(dst + APL) = make_uint2(u[i].y, u[i].w);
            }
#pragma unroll
            for (int i = 0; i < 8; i++) {
                int gr = r0 + rb + 64 + i * 8;
                u[i] = (gr < N_NODES) ? srcp[(size_t)gr * 16 + cc] : make_uint4(0, 0, 0, 0);
            }
        }
        // epilogue half 2 (mt 2..3)
#pragma unroll
        for (int mt = 2; mt < 4; mt++)
#pragma unroll
            for (int h = 0; h < 2; h++)
#pragma unroll
                for (int t = 0; t < 4; t++) {
                    int s0 = 3 * t, s1 = 3 * t + 1, s2 = 3 * t + 2;
                    float gi = acc[mt][s0 >> 1][h * 2 + (s0 & 1)] + bsv[s0];
                    float gc = acc[mt][s1 >> 1][h * 2 + (s1 & 1)] + bsv[s1];
                    float go = acc[mt][s2 >> 1][h * 2 + (s2 & 1)] + bsv[s2];
                    float I  = fsigmoid(gi);
                    float T  = ftanh(gc);
                    float Cn = I * T;
                    float O  = fsigmoid(go + wov[t] * Cn);
                    accO[mt][h][t] += O * ftanh(Cn);
                }
        if (more) {
#pragma unroll
            for (int i = 0; i < 8; i++) {
                char* dst = dst0 + (rb + 64 + i * 8) * ASTRIDE;
                *(uint2*)dst         = make_uint2(u[i].x, u[i].z);
                *(uint2*)(dst + APL) = make_uint2(u[i].y, u[i].w);
            }
        }
    }

    // ---- final output write (write-only, no RMW) ----
#pragma unroll
    for (int mt = 0; mt < 4; mt++)
#pragma unroll
        for (int h = 0; h < 2; h++) {
            int row = r0 + wm * 64 + mt * 16 + g + h * 8;
            if (row < N_NODES) {
                *(float4*)(out + (size_t)row * 64 + wn * 16 + tg * 4) =
                    make_float4(accO[mt][h][0], accO[mt][h][1],
                                accO[mt][h][2], accO[mt][h][3]);
            }
        }
}

// ---------------- launch ----------------
extern "C" void kernel_launch(void* const* d_in, const int* in_sizes, int n_in,
                              void* d_out, int out_size) {
    const float* X   = (const float*)d_in[0];
    const int*   ei  = (const int*)d_in[1];
    const float* ew  = (const float*)d_in[2];
    const float* Wx0 = (const float*)d_in[3];
    const float* Wx1 = (const float*)d_in[4];
    const float* bx  = (const float*)d_in[5];
    // d_in[6]=Wh0, d_in[7]=Wh1 unused (H=0 -> cheb(H)=bh)
    const float* bh  = (const float*)d_in[8];
    const float* wc  = (const float*)d_in[9];
    const float* bg  = (const float*)d_in[10];
    float* out = (float*)d_out;

    cudaFuncSetAttribute(gemm_fused, cudaFuncAttributeMaxDynamicSharedMemorySize, SMEM_BYTES);

    setup_kernel<<<(N_NODES + 255) / 256, 256>>>(Wx0, Wx1, bx, bh, bg, wc);   // 1
    transpose_kernel<<<(NF / 2 + 255) / 256, 256>>>(X);                        // 2
    deg_hist_kernel<<<(E_EDGES + 255) / 256, 256>>>(ei, ew);                   // 3
    scan_kernel<<<1, 1024>>>();                                                // 4
    wn_scatter_kernel<<<(E_EDGES + 255) / 256, 256>>>(ei, ew);                 // 5
    spmm_all_kernel<<<(N_NODES * 32 + 255) / 256, 256>>>();                    // 6
    gemm_fused<<<(N_NODES + 127) / 128, 256, SMEM_BYTES>>>(out);               // 7
}

// round 9
// speedup vs baseline: 2.3986x; 1.4557x over previous
#include <cuda_runtime.h>
#include <cuda_fp16.h>
#include <cstdint>

#define N_NODES 50000
#define FDIM    64
#define PER     8
#define E_EDGES 800000
#define NF      (N_NODES * FDIM)

// ---------------- scratch (static __device__ — no allocations) ----------------
// fp16 feature rows: per node 32 u32 (= 64 fp16), row = 128 bytes
__device__ uint32_t g_XH[PER * N_NODES * 32];   // X transposed, fp16 (~51 MB)
__device__ uint32_t g_TH[PER * N_NODES * 32];   // tx1 per period, fp16
__device__ float g_deg[N_NODES];
__device__ int   g_cnt[N_NODES];
__device__ int   g_rowptr[N_NODES + 1];
__device__ int   g_cursor[N_NODES];
__device__ int   g_esrc[E_EDGES];
__device__ float g_ewn[E_EDGES];
__device__ unsigned short g_Wbh[192 * 128];  // W packed [jphys][k], fp16 hi (permuted cols)
__device__ unsigned short g_Wbl[192 * 128];  // fp16 lo (residual)
__device__ float g_bs[192];                  // bx+bh+bg, jphys layout
__device__ float g_wo[64];                   // peephole wc[2], logical f

// ---------------- small helpers ----------------
__device__ __forceinline__ float fsigmoid(float x) {
    return __fdividef(1.0f, 1.0f + __expf(-x));
}
__device__ __forceinline__ float ftanh(float x) {
    x = fminf(fmaxf(x, -15.0f), 15.0f);
    float e = __expf(2.0f * x);
    return __fdividef(e - 1.0f, e + 1.0f);
}
__device__ __forceinline__ uint32_t packh2(float a, float b) {
    __half2 h = __floats2half2_rn(a, b);
    return *reinterpret_cast<uint32_t*>(&h);
}

// physical B column jphys -> logical (feature f, gate g3 in {0:i,1:c,2:o})
__device__ __forceinline__ void jmap(int jp, int& f, int& g3) {
    int wn = jp / 48, rem = jp % 48;
    int nt = rem >> 3, r8 = rem & 7, tg = r8 >> 1, e = r8 & 1;
    int slot = nt * 2 + e;
    f  = wn * 16 + tg * 4 + slot / 3;
    g3 = slot % 3;
}

// mma.sync m16n8k16 fp16 -> f32 acc (sm_80+ baseline PTX)
__device__ __forceinline__ void mma_f16(float* c,
                                        uint32_t a0, uint32_t a1, uint32_t a2, uint32_t a3,
                                        uint32_t b0, uint32_t b1) {
    asm volatile(
        "mma.sync.aligned.m16n8k16.row.col.f32.f16.f16.f32 "
        "{%0,%1,%2,%3}, {%4,%5,%6,%7}, {%8,%9}, {%0,%1,%2,%3};"
        : "+f"(c[0]), "+f"(c[1]), "+f"(c[2]), "+f"(c[3])
        : "r"(a0), "r"(a1), "r"(a2), "r"(a3), "r"(b0), "r"(b1));
}

// ---------------- setup: zero + pack_w + pack_b in ONE kernel ----------------
__global__ void setup_kernel(const float* __restrict__ Wx0, const float* __restrict__ Wx1,
                             const float* __restrict__ bx, const float* __restrict__ bh,
                             const float* __restrict__ bg, const float* __restrict__ wc) {
    int t = blockIdx.x * blockDim.x + threadIdx.x;
    if (t < N_NODES) { g_deg[t] = 0.0f; g_cnt[t] = 0; }
    if (t < 192 * 128) {
        int jp = t >> 7, k = t & 127;
        int f, g3; jmap(jp, f, g3);
        int gg = (g3 == 0) ? 0 : ((g3 == 1) ? 2 : 3);
        float v = (k < 64) ? Wx0[gg * 4096 + k * 64 + f]
                           : Wx1[gg * 4096 + (k - 64) * 64 + f];
        __half h = __float2half_rn(v);
        float  hf = __half2float(h);
        __half l = __float2half_rn(v - hf);
        g_Wbh[t] = *reinterpret_cast<unsigned short*>(&h);
        g_Wbl[t] = *reinterpret_cast<unsigned short*>(&l);
    }
    if (t < 192) {
        int f, g3; jmap(t, f, g3);
        int gg = (g3 == 0) ? 0 : ((g3 == 1) ? 2 : 3);
        g_bs[t] = bx[gg * 64 + f] + bh[gg * 64 + f] + bg[gg * 64 + f];
    }
    if (t < 64) g_wo[t] = wc[2 * 64 + t];
}

// X: [N, F, P] fp32 -> g_XH[p][n][pair] fp16
__global__ void transpose_kernel(const float* __restrict__ X) {
    int t = blockIdx.x * blockDim.x + threadIdx.x;
    if (t >= NF / 2) return;
    int n = t >> 5, j = t & 31;
    const float4* src = reinterpret_cast<const float4*>(X + ((size_t)n * 64 + 2 * j) * 8);
    float4 v0 = src[0], v1 = src[1], v2 = src[2], v3 = src[3];
    float f0[8] = {v0.x, v0.y, v0.z, v0.w, v1.x, v1.y, v1.z, v1.w};
    float f1[8] = {v2.x, v2.y, v2.z, v2.w, v3.x, v3.y, v3.z, v3.w};
#pragma unroll
    for (int p = 0; p < PER; p++)
        g_XH[((size_t)p * N_NODES + n) * 32 + j] = packh2(f0[p], f1[p]);
}

__global__ void deg_hist_kernel(const int* __restrict__ ei, const float* __restrict__ ew) {
    int e = blockIdx.x * blockDim.x + threadIdx.x;
    if (e >= E_EDGES) return;
    atomicAdd(&g_deg[ei[e]], ew[e]);
    atomicAdd(&g_cnt[ei[E_EDGES + e]], 1);
}

// single-block scan, thread-local chunks: 2 passes, block-scan of 1024 partials
__global__ void scan_kernel() {
    __shared__ int wsum[32];
    const int CH = 49;   // ceil(50000 / 1024)
    int tid = threadIdx.x, lane = tid & 31, wid = tid >> 5;
    int base = tid * CH;
    int s = 0;
#pragma unroll 7
    for (int i = 0; i < CH; i++) {
        int idx = base + i;
        if (idx < N_NODES) s += g_cnt[idx];
    }
    int x = s;
#pragma unroll
    for (int off = 1; off < 32; off <<= 1) {
        int t = __shfl_up_sync(0xffffffffu, x, off);
        if (lane >= off) x += t;
    }
    if (lane == 31) wsum[wid] = x;
    __syncthreads();
    if (wid == 0) {
        int v = wsum[lane];
        int y = v;
#pragma unroll
        for (int off = 1; off < 32; off <<= 1) {
            int t = __shfl_up_sync(0xffffffffu, y, off);
            if (lane >= off) y += t;
        }
        wsum[lane] = y - v;   // exclusive warp offset
    }
    __syncthreads();
    int run = (x - s) + wsum[wid];   // exclusive prefix for this thread's chunk
#pragma unroll 7
    for (int i = 0; i < CH; i++) {
        int idx = base + i;
        if (idx < N_NODES) {
            g_rowptr[idx] = run;
            g_cursor[idx] = run;
            run += g_cnt[idx];
        }
    }
    if (tid == 1023) g_rowptr[N_NODES] = run;
}

__global__ void wn_scatter_kernel(const int* __restrict__ ei, const float* __restrict__ ew) {
    int e = blockIdx.x * blockDim.x + threadIdx.x;
    if (e >= E_EDGES) return;
    int s = ei[e], d = ei[E_EDGES + e];
    float ds = g_deg[s], dd = g_deg[d];
    float is = (ds > 0.0f) ? rsqrtf(fmaxf(ds, 1e-12f)) : 0.0f;
    float id = (dd > 0.0f) ? rsqrtf(fmaxf(dd, 1e-12f)) : 0.0f;
    float w = -is * ew[e] * id;
    int pos = atomicAdd(&g_cursor[d], 1);
    g_esrc[pos] = s;
    g_ewn[pos] = w;
}

// ---------------- pull SpMM, ALL periods, fp16 rows (128B gather per row) ----------------
__global__ void __launch_bounds__(256) spmm_all_kernel() {
    int warp = (blockIdx.x * blockDim.x + threadIdx.x) >> 5;
    int lane = threadIdx.x & 31;
    if (warp >= N_NODES) return;
    int beg = g_rowptr[warp], end = g_rowptr[warp + 1];
    float ax[PER], ay[PER];
#pragma unroll
    for (int p = 0; p < PER; p++) { ax[p] = 0.0f; ay[p] = 0.0f; }
    for (int e = beg; e < end; e++) {
        int s = g_esrc[e];
        float w = g_ewn[e];
        const uint32_t* base = g_XH + (size_t)s * 32 + lane;
        uint32_t u[PER];
#pragma unroll
        for (int p = 0; p < PER; p++) u[p] = base[(size_t)p * N_NODES * 32];
#pragma unroll
        for (int p = 0; p < PER; p++) {
            float2 v = __half22float2(*reinterpret_cast<__half2*>(&u[p]));
            ax[p] += w * v.x;
            ay[p] += w * v.y;
        }
    }
#pragma unroll
    for (int p = 0; p < PER; p++)
        g_TH[((size_t)p * N_NODES + warp) * 32 + lane] = packh2(ax[p], ay[p]);
}

// ---------------- fused mma.sync GEMM: all 8 periods per block, fp16 2-pass ----------------
// smem: A [row 128][k 128] fp16, row stride 272B (256B data); B [jphys 192][k 128] fp16 hi/lo
#define ASTRIDE 272
#define BSTRIDE 272
#define BPL     52224
#define SM_A    0
#define SM_B    34816
#define SMEM_BYTES (34816 + 104448)

__global__ void __launch_bounds__(256, 1) gemm_fused(float* __restrict__ out) {
    extern __shared__ char smem[];
    int tid = threadIdx.x;
    int wid = tid >> 5, lane = tid & 31;
    int g = lane >> 2, tg = lane & 3;
    int wm = wid & 1;          // warp row: 0/1 -> rows 0-63 / 64-127
    int wn = wid >> 1;         // warp col: 0..3 -> jphys base 48*wn
    int r0 = blockIdx.x * 128;

    // ---- B copy (once): [192][128] fp16 hi + lo ----
    for (int it = tid; it < 3072; it += 256) {
        int j = it >> 4, c = it & 15;
        *(uint4*)(smem + SM_B + j * BSTRIDE + c * 16) = ((const uint4*)g_Wbh)[j * 16 + c];
        *(uint4*)(smem + SM_B + BPL + j * BSTRIDE + c * 16) = ((const uint4*)g_Wbl)[j * 16 + c];
    }

    // ---- per-thread biases (thread-local epilogue via column permutation) ----
    float bsv[12], wov[4];
#pragma unroll
    for (int s = 0; s < 12; s++) {
        int nt = s >> 1, e = s & 1;
        bsv[s] = g_bs[wn * 48 + nt * 8 + tg * 2 + e];
    }
#pragma unroll
    for (int t = 0; t < 4; t++) wov[t] = g_wo[wn * 16 + tg * 4 + t];

    float accO[4][2][4];
#pragma unroll
    for (int mt = 0; mt < 4; mt++)
#pragma unroll
        for (int h = 0; h < 2; h++)
#pragma unroll
            for (int t = 0; t < 4; t++) accO[mt][h][t] = 0.0f;

    // copyA pieces: A row = 256B = 16 uint4 (cc<8: X fp16, cc>=8: tx1 fp16)
    int cc = tid & 15, rb = tid >> 4;   // rows rb + 16*i, i<8
    char* dst0 = smem + SM_A + cc * 16;
    int idx4 = (cc < 8) ? cc : (cc - 8);

    // ---- initial A copy (p = 0) ----
    {
        const uint32_t* srcbase = (cc < 8) ? g_XH : g_TH;
#pragma unroll
        for (int i = 0; i < 8; i++) {
            int r = rb + i * 16;
            int gr = r0 + r;
            uint4 u = make_uint4(0, 0, 0, 0);
            if (gr < N_NODES)
                u = ((const uint4*)(srcbase + (size_t)gr * 32))[idx4];
            *(uint4*)(dst0 + r * ASTRIDE) = u;
        }
    }

    for (int p = 0; p < PER; p++) {
        __syncthreads();   // A(p) visible

        // ---- mma: acc[mt][nt][q], 2-pass fp16 (A x Bh, A x Bl) ----
        float acc[4][6][4];
#pragma unroll
        for (int mt = 0; mt < 4; mt++)
#pragma unroll
            for (int nt = 0; nt < 6; nt++)
#pragma unroll
                for (int q = 0; q < 4; q++) acc[mt][nt][q] = 0.0f;

#pragma unroll
        for (int ks = 0; ks < 8; ks++) {
            uint32_t a[4][4];
#pragma unroll
            for (int mt = 0; mt < 4; mt++) {
                const char* ab = smem + SM_A + (wm * 64 + mt * 16 + g) * ASTRIDE
                               + ks * 32 + tg * 4;
                a[mt][0] = *(const uint32_t*)(ab);
                a[mt][1] = *(const uint32_t*)(ab + 8 * ASTRIDE);
                a[mt][2] = *(const uint32_t*)(ab + 16);
                a[mt][3] = *(const uint32_t*)(ab + 8 * ASTRIDE + 16);
            }
#pragma unroll
            for (int nt = 0; nt < 6; nt++) {
                const char* bb = smem + SM_B + (wn * 48 + nt * 8 + g) * BSTRIDE
                               + ks * 32 + tg * 4;
                uint32_t bh0 = *(const uint32_t*)(bb);
                uint32_t bh1 = *(const uint32_t*)(bb + 16);
                uint32_t bl0 = *(const uint32_t*)(bb + BPL);
                uint32_t bl1 = *(const uint32_t*)(bb + BPL + 16);
#pragma unroll
                for (int mt = 0; mt < 4; mt++) {
                    mma_f16(acc[mt][nt], a[mt][0], a[mt][1], a[mt][2], a[mt][3], bh0, bh1);
                    mma_f16(acc[mt][nt], a[mt][0], a[mt][1], a[mt][2], a[mt][3], bl0, bl1);
                }
            }
        }
        __syncthreads();   // A reads done; safe to overwrite A

        // ---- prefetch A(p+1) into regs, thread-local epilogue, store ----
        bool more = (p + 1 < PER);
        uint4 u[8];
        if (more) {
            const uint32_t* srcbase = ((cc < 8) ? g_XH : g_TH)
                                    + (size_t)(p + 1) * N_NODES * 32;
#pragma unroll
            for (int i = 0; i < 8; i++) {
                int gr = r0 + rb + i * 16;
                u[i] = (gr < N_NODES) ? ((const uint4*)(srcbase + (size_t)gr * 32))[idx4]
                                      : make_uint4(0, 0, 0, 0);
            }
        }
#pragma unroll
        for (int mt = 0; mt < 4; mt++)
#pragma unroll
            for (int h = 0; h < 2; h++)
#pragma unroll
                for (int t = 0; t < 4; t++) {
                    int s0 = 3 * t, s1 = 3 * t + 1, s2 = 3 * t + 2;
                    float gi = acc[mt][s0 >> 1][h * 2 + (s0 & 1)] + bsv[s0];
                    float gc = acc[mt][s1 >> 1][h * 2 + (s1 & 1)] + bsv[s1];
                    float go = acc[mt][s2 >> 1][h * 2 + (s2 & 1)] + bsv[s2];
                    float I  = fsigmoid(gi);
                    float T  = ftanh(gc);
                    float Cn = I * T;
                    float O  = fsigmoid(go + wov[t] * Cn);
                    accO[mt][h][t] += O * ftanh(Cn);
                }
        if (more) {
#pragma unroll
            for (int i = 0; i < 8; i++)
                *(uint4*)(dst0 + (rb + i * 16) * ASTRIDE) = u[i];
        }
    }

    // ---- final output write (write-only, no RMW) ----
#pragma unroll
    for (int mt = 0; mt < 4; mt++)
#pragma unroll
        for (int h = 0; h < 2; h++) {
            int row = r0 + wm * 64 + mt * 16 + g + h * 8;
            if (row < N_NODES) {
                *(float4*)(out + (size_t)row * 64 + wn * 16 + tg * 4) =
                    make_float4(accO[mt][h][0], accO[mt][h][1],
                                accO[mt][h][2], accO[mt][h][3]);
            }
        }
}

// ---------------- launch ----------------
extern "C" void kernel_launch(void* const* d_in, const int* in_sizes, int n_in,
                              void* d_out, int out_size) {
    const float* X   = (const float*)d_in[0];
    const int*   ei  = (const int*)d_in[1];
    const float* ew  = (const float*)d_in[2];
    const float* Wx0 = (const float*)d_in[3];
    const float* Wx1 = (const float*)d_in[4];
    const float* bx  = (const float*)d_in[5];
    // d_in[6]=Wh0, d_in[7]=Wh1 unused (H=0 -> cheb(H)=bh)
    const float* bh  = (const float*)d_in[8];
    const float* wc  = (const float*)d_in[9];
    const float* bg  = (const float*)d_in[10];
    float* out = (float*)d_out;

    cudaFuncSetAttribute(gemm_fused, cudaFuncAttributeMaxDynamicSharedMemorySize, SMEM_BYTES);

    setup_kernel<<<(N_NODES + 255) / 256, 256>>>(Wx0, Wx1, bx, bh, bg, wc);   // 1
    transpose_kernel<<<(NF / 2 + 255) / 256, 256>>>(X);                        // 2
    deg_hist_kernel<<<(E_EDGES + 255) / 256, 256>>>(ei, ew);                   // 3
    scan_kernel<<<1, 1024>>>();                                                // 4
    wn_scatter_kernel<<<(E_EDGES + 255) / 256, 256>>>(ei, ew);                 // 5
    spmm_all_kernel<<<(N_NODES * 32 + 255) / 256, 256>>>();                    // 6
    gemm_fused<<<(N_NODES + 127) / 128, 256, SMEM_BYTES>>>(out);               // 7
}

// round 10
// speedup vs baseline: 3.3955x; 1.4156x over previous
#include <cuda_runtime.h>
#include <cuda_fp16.h>
#include <cstdint>

#define N_NODES 50000
#define FDIM    64
#define PER     8
#define E_EDGES 800000
#define NF      (N_NODES * FDIM)

// ---------------- scratch (static __device__ — no allocations) ----------------
// fp16 feature rows: per node 32 u32 (= 64 fp16), row = 128 bytes
__device__ uint32_t g_XH[PER * N_NODES * 32];   // X transposed, fp16 (~51 MB)
__device__ uint32_t g_TH[PER * N_NODES * 32];   // tx1 per period, fp16
__device__ float g_deg[N_NODES];
__device__ __align__(16) int g_cnt[N_NODES];
__device__ int   g_rowptr[N_NODES + 1];
__device__ int   g_cursor[N_NODES];
__device__ int   g_esrc[E_EDGES];
__device__ float g_ewn[E_EDGES];
__device__ unsigned short g_Wh[192 * 128];   // W packed [jphys][k], fp16 (permuted cols)
__device__ float g_bs[192];                  // bx+bh+bg, jphys layout
__device__ float g_wo[64];                   // peephole wc[2], logical f

// ---------------- small helpers ----------------
__device__ __forceinline__ float fsigmoid(float x) {
    return __fdividef(1.0f, 1.0f + __expf(-x));
}
__device__ __forceinline__ float ftanh(float x) {
    x = fminf(fmaxf(x, -15.0f), 15.0f);
    float e = __expf(2.0f * x);
    return __fdividef(e - 1.0f, e + 1.0f);
}
__device__ __forceinline__ uint32_t packh2(float a, float b) {
    __half2 h = __floats2half2_rn(a, b);
    return *reinterpret_cast<uint32_t*>(&h);
}

// physical B column jphys -> logical (feature f, gate g3 in {0:i,1:c,2:o})
__device__ __forceinline__ void jmap(int jp, int& f, int& g3) {
    int wn = jp / 48, rem = jp % 48;
    int nt = rem >> 3, r8 = rem & 7, tg = r8 >> 1, e = r8 & 1;
    int slot = nt * 2 + e;
    f  = wn * 16 + tg * 4 + slot / 3;
    g3 = slot % 3;
}

// mma.sync m16n8k16 fp16 -> f32 acc (sm_80+ baseline PTX)
__device__ __forceinline__ void mma_f16(float* c,
                                        uint32_t a0, uint32_t a1, uint32_t a2, uint32_t a3,
                                        uint32_t b0, uint32_t b1) {
    asm volatile(
        "mma.sync.aligned.m16n8k16.row.col.f32.f16.f16.f32 "
        "{%0,%1,%2,%3}, {%4,%5,%6,%7}, {%8,%9}, {%0,%1,%2,%3};"
        : "+f"(c[0]), "+f"(c[1]), "+f"(c[2]), "+f"(c[3])
        : "r"(a0), "r"(a1), "r"(a2), "r"(a3), "r"(b0), "r"(b1));
}

// ---------------- setup: zero + pack_w + pack_b in ONE kernel ----------------
__global__ void setup_kernel(const float* __restrict__ Wx0, const float* __restrict__ Wx1,
                             const float* __restrict__ bx, const float* __restrict__ bh,
                             const float* __restrict__ bg, const float* __restrict__ wc) {
    int t = blockIdx.x * blockDim.x + threadIdx.x;
    if (t < N_NODES) { g_deg[t] = 0.0f; g_cnt[t] = 0; }
    if (t < 192 * 128) {
        int jp = t >> 7, k = t & 127;
        int f, g3; jmap(jp, f, g3);
        int gg = (g3 == 0) ? 0 : ((g3 == 1) ? 2 : 3);
        float v = (k < 64) ? Wx0[gg * 4096 + k * 64 + f]
                           : Wx1[gg * 4096 + (k - 64) * 64 + f];
        __half h = __float2half_rn(v);
        g_Wh[t] = *reinterpret_cast<unsigned short*>(&h);
    }
    if (t < 192) {
        int f, g3; jmap(t, f, g3);
        int gg = (g3 == 0) ? 0 : ((g3 == 1) ? 2 : 3);
        g_bs[t] = bx[gg * 64 + f] + bh[gg * 64 + f] + bg[gg * 64 + f];
    }
    if (t < 64) g_wo[t] = wc[2 * 64 + t];
}

// X: [N, F, P] fp32 -> g_XH[p][n][pair] fp16
__global__ void transpose_kernel(const float* __restrict__ X) {
    int t = blockIdx.x * blockDim.x + threadIdx.x;
    if (t >= NF / 2) return;
    int n = t >> 5, j = t & 31;
    const float4* src = reinterpret_cast<const float4*>(X + ((size_t)n * 64 + 2 * j) * 8);
    float4 v0 = src[0], v1 = src[1], v2 = src[2], v3 = src[3];
    float f0[8] = {v0.x, v0.y, v0.z, v0.w, v1.x, v1.y, v1.z, v1.w};
    float f1[8] = {v2.x, v2.y, v2.z, v2.w, v3.x, v3.y, v3.z, v3.w};
#pragma unroll
    for (int p = 0; p < PER; p++)
        g_XH[((size_t)p * N_NODES + n) * 32 + j] = packh2(f0[p], f1[p]);
}

__global__ void deg_hist_kernel(const int* __restrict__ ei, const float* __restrict__ ew) {
    int e = blockIdx.x * blockDim.x + threadIdx.x;
    if (e >= E_EDGES) return;
    atomicAdd(&g_deg[ei[e]], ew[e]);
    atomicAdd(&g_cnt[ei[E_EDGES + e]], 1);
}

// single-block scan: stage g_cnt in smem (coalesced), thread-local chunk scan from
// smem (conflict-free: 49 coprime 32), in-place prefix write-back, coalesced copy out.
#define SCAN_SMEM (N_NODES * 4)
__global__ void scan_kernel() {
    extern __shared__ int scnt[];   // 50000 ints = 200KB
    __shared__ int wsum[32];
    const int CH = 49;              // ceil(50000 / 1024)
    int tid = threadIdx.x, lane = tid & 31, wid = tid >> 5;

    // coalesced load g_cnt -> smem (12500 int4)
    for (int i = tid; i < N_NODES / 4; i += 1024)
        ((int4*)scnt)[i] = ((const int4*)g_cnt)[i];
    __syncthreads();

    // thread-local sum over own chunk
    int base = tid * CH;
    int s = 0;
#pragma unroll 7
    for (int i = 0; i < CH; i++) {
        int idx = base + i;
        if (idx < N_NODES) s += scnt[idx];
    }
    // block scan of 1024 partials
    int x = s;
#pragma unroll
    for (int off = 1; off < 32; off <<= 1) {
        int t = __shfl_up_sync(0xffffffffu, x, off);
        if (lane >= off) x += t;
    }
    if (lane == 31) wsum[wid] = x;
    __syncthreads();
    if (wid == 0) {
        int v = wsum[lane];
        int y = v;
#pragma unroll
        for (int off = 1; off < 32; off <<= 1) {
            int t = __shfl_up_sync(0xffffffffu, y, off);
            if (lane >= off) y += t;
        }
        wsum[lane] = y - v;
    }
    __syncthreads();
    // in-place exclusive prefix within own chunk
    int run = (x - s) + wsum[wid];
    int total = (tid == 1023) ? run + s : 0;
#pragma unroll 7
    for (int i = 0; i < CH; i++) {
        int idx = base + i;
        if (idx < N_NODES) {
            int c = scnt[idx];
            scnt[idx] = run;
            run += c;
        }
    }
    __syncthreads();
    // coalesced copy out
    for (int i = tid; i < N_NODES / 4; i += 1024) {
        int4 v = ((const int4*)scnt)[i];
        ((int4*)g_rowptr)[i] = v;
        ((int4*)g_cursor)[i] = v;
    }
    if (tid == 1023) g_rowptr[N_NODES] = total;
}

__global__ void wn_scatter_kernel(const int* __restrict__ ei, const float* __restrict__ ew) {
    int e = blockIdx.x * blockDim.x + threadIdx.x;
    if (e >= E_EDGES) return;
    int s = ei[e], d = ei[E_EDGES + e];
    float ds = g_deg[s], dd = g_deg[d];
    float is = (ds > 0.0f) ? rsqrtf(fmaxf(ds, 1e-12f)) : 0.0f;
    float id = (dd > 0.0f) ? rsqrtf(fmaxf(dd, 1e-12f)) : 0.0f;
    float w = -is * ew[e] * id;
    int pos = atomicAdd(&g_cursor[d], 1);
    g_esrc[pos] = s;
    g_ewn[pos] = w;
}

// ---------------- pull SpMM, ALL periods, fp16 rows (128B gather per row) ----------------
__global__ void __launch_bounds__(256) spmm_all_kernel() {
    int warp = (blockIdx.x * blockDim.x + threadIdx.x) >> 5;
    int lane = threadIdx.x & 31;
    if (warp >= N_NODES) return;
    int beg = g_rowptr[warp], end = g_rowptr[warp + 1];
    float ax[PER], ay[PER];
#pragma unroll
    for (int p = 0; p < PER; p++) { ax[p] = 0.0f; ay[p] = 0.0f; }
    for (int e = beg; e < end; e++) {
        int s = g_esrc[e];
        float w = g_ewn[e];
        const uint32_t* base = g_XH + (size_t)s * 32 + lane;
        uint32_t u[PER];
#pragma unroll
        for (int p = 0; p < PER; p++) u[p] = base[(size_t)p * N_NODES * 32];
#pragma unroll
        for (int p = 0; p < PER; p++) {
            float2 v = __half22float2(*reinterpret_cast<__half2*>(&u[p]));
            ax[p] += w * v.x;
            ay[p] += w * v.y;
        }
    }
#pragma unroll
    for (int p = 0; p < PER; p++)
        g_TH[((size_t)p * N_NODES + warp) * 32 + lane] = packh2(ax[p], ay[p]);
}

// ---------------- fused mma.sync GEMM: all 8 periods per block, 1-pass fp16 ----------------
// smem: A [row 128][k 128] fp16, row stride 272B (256B data); B [jphys 192][k 128] fp16
#define ASTRIDE 272
#define BSTRIDE 272
#define SM_A    0
#define SM_B    34816
#define SMEM_BYTES (34816 + 52224)

__global__ void __launch_bounds__(256, 1) gemm_fused(float* __restrict__ out) {
    extern __shared__ char smem[];
    int tid = threadIdx.x;
    int wid = tid >> 5, lane = tid & 31;
    int g = lane >> 2, tg = lane & 3;
    int wm = wid & 1;          // warp row: 0/1 -> rows 0-63 / 64-127
    int wn = wid >> 1;         // warp col: 0..3 -> jphys base 48*wn
    int r0 = blockIdx.x * 128;

    // ---- B copy (once): [192][128] fp16 ----
    for (int it = tid; it < 1536; it += 256) {
        int j = it >> 3, c = it & 7;
        *(uint4*)(smem + SM_B + j * BSTRIDE + c * 32 + (tid & 0) ) =
            ((const uint4*)g_Wh)[j * 16 + c * 2];
        *(uint4*)(smem + SM_B + j * BSTRIDE + c * 32 + 16) =
            ((const uint4*)g_Wh)[j * 16 + c * 2 + 1];
    }

    // ---- per-thread biases (thread-local epilogue via column permutation) ----
    float bsv[12], wov[4];
#pragma unroll
    for (int s = 0; s < 12; s++) {
        int nt = s >> 1, e = s & 1;
        bsv[s] = g_bs[wn * 48 + nt * 8 + tg * 2 + e];
    }
#pragma unroll
    for (int t = 0; t < 4; t++) wov[t] = g_wo[wn * 16 + tg * 4 + t];

    float accO[4][2][4];
#pragma unroll
    for (int mt = 0; mt < 4; mt++)
#pragma unroll
        for (int h = 0; h < 2; h++)
#pragma unroll
            for (int t = 0; t < 4; t++) accO[mt][h][t] = 0.0f;

    // copyA pieces: A row = 256B = 16 uint4 (cc<8: X fp16, cc>=8: tx1 fp16)
    int cc = tid & 15, rb = tid >> 4;   // rows rb + 16*i, i<8
    char* dst0 = smem + SM_A + cc * 16;
    int idx4 = (cc < 8) ? cc : (cc - 8);

    // ---- initial A copy (p = 0) ----
    {
        const uint32_t* srcbase = (cc < 8) ? g_XH : g_TH;
#pragma unroll
        for (int i = 0; i < 8; i++) {
            int r = rb + i * 16;
            int gr = r0 + r;
            uint4 u = make_uint4(0, 0, 0, 0);
            if (gr < N_NODES)
                u = ((const uint4*)(srcbase + (size_t)gr * 32))[idx4];
            *(uint4*)(dst0 + r * ASTRIDE) = u;
        }
    }

    for (int p = 0; p < PER; p++) {
        __syncthreads();   // A(p) visible

        // ---- mma: acc[mt][nt][q], single fp16 pass ----
        float acc[4][6][4];
#pragma unroll
        for (int mt = 0; mt < 4; mt++)
#pragma unroll
            for (int nt = 0; nt < 6; nt++)
#pragma unroll
                for (int q = 0; q < 4; q++) acc[mt][nt][q] = 0.0f;

#pragma unroll
        for (int ks = 0; ks < 8; ks++) {
            uint32_t a[4][4];
#pragma unroll
            for (int mt = 0; mt < 4; mt++) {
                const char* ab = smem + SM_A + (wm * 64 + mt * 16 + g) * ASTRIDE
                               + ks * 32 + tg * 4;
                a[mt][0] = *(const uint32_t*)(ab);
                a[mt][1] = *(const uint32_t*)(ab + 8 * ASTRIDE);
                a[mt][2] = *(const uint32_t*)(ab + 16);
                a[mt][3] = *(const uint32_t*)(ab + 8 * ASTRIDE + 16);
            }
#pragma unroll
            for (int nt = 0; nt < 6; nt++) {
                const char* bb = smem + SM_B + (wn * 48 + nt * 8 + g) * BSTRIDE
                               + ks * 32 + tg * 4;
                uint32_t b0 = *(const uint32_t*)(bb);
                uint32_t b1 = *(const uint32_t*)(bb + 16);
#pragma unroll
                for (int mt = 0; mt < 4; mt++)
                    mma_f16(acc[mt][nt], a[mt][0], a[mt][1], a[mt][2], a[mt][3], b0, b1);
            }
        }
        __syncthreads();   // A reads done; safe to overwrite A

        // ---- prefetch A(p+1) into regs, thread-local epilogue, store ----
        bool more = (p + 1 < PER);
        uint4 u[8];
        if (more) {
            const uint32_t* srcbase = ((cc < 8) ? g_XH : g_TH)
                                    + (size_t)(p + 1) * N_NODES * 32;
#pragma unroll
            for (int i = 0; i < 8; i++) {
                int gr = r0 + rb + i * 16;
                u[i] = (gr < N_NODES) ? ((const uint4*)(srcbase + (size_t)gr * 32))[idx4]
                                      : make_uint4(0, 0, 0, 0);
            }
        }
#pragma unroll
        for (int mt = 0; mt < 4; mt++)
#pragma unroll
            for (int h = 0; h < 2; h++)
#pragma unroll
                for (int t = 0; t < 4; t++) {
                    int s0 = 3 * t, s1 = 3 * t + 1, s2 = 3 * t + 2;
                    float gi = acc[mt][s0 >> 1][h * 2 + (s0 & 1)] + bsv[s0];
                    float gc = acc[mt][s1 >> 1][h * 2 + (s1 & 1)] + bsv[s1];
                    float go = acc[mt][s2 >> 1][h * 2 + (s2 & 1)] + bsv[s2];
                    float I  = fsigmoid(gi);
                    float T  = ftanh(gc);
                    float Cn = I * T;
                    float O  = fsigmoid(go + wov[t] * Cn);
                    accO[mt][h][t] += O * ftanh(Cn);
                }
        if (more) {
#pragma unroll
            for (int i = 0; i < 8; i++)
                *(uint4*)(dst0 + (rb + i * 16) * ASTRIDE) = u[i];
        }
    }

    // ---- final output write (write-only, no RMW) ----
#pragma unroll
    for (int mt = 0; mt < 4; mt++)
#pragma unroll
        for (int h = 0; h < 2; h++) {
            int row = r0 + wm * 64 + mt * 16 + g + h * 8;
            if (row < N_NODES) {
                *(float4*)(out + (size_t)row * 64 + wn * 16 + tg * 4) =
                    make_float4(accO[mt][h][0], accO[mt][h][1],
                                accO[mt][h][2], accO[mt][h][3]);
            }
        }
}

// ---------------- launch ----------------
extern "C" void kernel_launch(void* const* d_in, const int* in_sizes, int n_in,
                              void* d_out, int out_size) {
    const float* X   = (const float*)d_in[0];
    const int*   ei  = (const int*)d_in[1];
    const float* ew  = (const float*)d_in[2];
    const float* Wx0 = (const float*)d_in[3];
    const float* Wx1 = (const float*)d_in[4];
    const float* bx  = (const float*)d_in[5];
    // d_in[6]=Wh0, d_in[7]=Wh1 unused (H=0 -> cheb(H)=bh)
    const float* bh  = (const float*)d_in[8];
    const float* wc  = (const float*)d_in[9];
    const float* bg  = (const float*)d_in[10];
    float* out = (float*)d_out;

    cudaFuncSetAttribute(gemm_fused, cudaFuncAttributeMaxDynamicSharedMemorySize, SMEM_BYTES);
    cudaFuncSetAttribute(scan_kernel, cudaFuncAttributeMaxDynamicSharedMemorySize, SCAN_SMEM);

    setup_kernel<<<(N_NODES + 255) / 256, 256>>>(Wx0, Wx1, bx, bh, bg, wc);   // 1
    transpose_kernel<<<(NF / 2 + 255) / 256, 256>>>(X);                        // 2
    deg_hist_kernel<<<(E_EDGES + 255) / 256, 256>>>(ei, ew);                   // 3
    scan_kernel<<<1, 1024, SCAN_SMEM>>>();                                     // 4
    wn_scatter_kernel<<<(E_EDGES + 255) / 256, 256>>>(ei, ew);                 // 5
    spmm_all_kernel<<<(N_NODES * 32 + 255) / 256, 256>>>();                    // 6
    gemm_fused<<<(N_NODES + 127) / 128, 256, SMEM_BYTES>>>(out);               // 7
}

// round 11
// speedup vs baseline: 3.6347x; 1.0704x over previous
#include <cuda_runtime.h>
#include <cuda_fp16.h>
#include <cstdint>

#define N_NODES 50000
#define FDIM    64
#define PER     8
#define E_EDGES 800000
#define NF      (N_NODES * FDIM)

// ---------------- scratch (static __device__ — no allocations) ----------------
// fp16 feature rows: per node 32 u32 (= 64 fp16), row = 128 bytes
__device__ uint32_t g_XH[PER * N_NODES * 32];   // X transposed, fp16 (~51 MB)
__device__ uint32_t g_TH[PER * N_NODES * 32];   // tx1 per period, fp16
__device__ float g_deg[N_NODES];
__device__ __align__(16) int g_cnt[N_NODES];
__device__ int   g_rowptr[N_NODES + 1];
__device__ int   g_cursor[N_NODES];
__device__ int   g_esrc[E_EDGES];
__device__ float g_ewn[E_EDGES];
__device__ unsigned short g_Wh[192 * 128];   // W packed [jphys][k], fp16 (permuted cols)
__device__ float g_bs[192];                  // bx+bh+bg, jphys layout
__device__ float g_wo[64];                   // peephole wc[2], logical f

// ---------------- small helpers ----------------
__device__ __forceinline__ float tanh_fast(float x) {
    float r; asm("tanh.approx.f32 %0, %1;" : "=f"(r) : "f"(x)); return r;
}
__device__ __forceinline__ float fsigmoid(float x) {           // 1 MUFU + 1 FMA
    return fmaf(tanh_fast(0.5f * x), 0.5f, 0.5f);
}
__device__ __forceinline__ float ftanh(float x) {              // 1 MUFU
    return tanh_fast(x);
}
__device__ __forceinline__ uint32_t packh2(float a, float b) {
    __half2 h = __floats2half2_rn(a, b);
    return *reinterpret_cast<uint32_t*>(&h);
}

// physical B column jphys -> logical (feature f, gate g3 in {0:i,1:c,2:o})
__device__ __forceinline__ void jmap(int jp, int& f, int& g3) {
    int wn = jp / 48, rem = jp % 48;
    int nt = rem >> 3, r8 = rem & 7, tg = r8 >> 1, e = r8 & 1;
    int slot = nt * 2 + e;
    f  = wn * 16 + tg * 4 + slot / 3;
    g3 = slot % 3;
}

// mma.sync m16n8k16 fp16 -> f32 acc (sm_80+ baseline PTX)
__device__ __forceinline__ void mma_f16(float* c,
                                        uint32_t a0, uint32_t a1, uint32_t a2, uint32_t a3,
                                        uint32_t b0, uint32_t b1) {
    asm volatile(
        "mma.sync.aligned.m16n8k16.row.col.f32.f16.f16.f32 "
        "{%0,%1,%2,%3}, {%4,%5,%6,%7}, {%8,%9}, {%0,%1,%2,%3};"
        : "+f"(c[0]), "+f"(c[1]), "+f"(c[2]), "+f"(c[3])
        : "r"(a0), "r"(a1), "r"(a2), "r"(a3), "r"(b0), "r"(b1));
}

// ---------------- setup: zero + pack_w + pack_b in ONE kernel ----------------
__global__ void setup_kernel(const float* __restrict__ Wx0, const float* __restrict__ Wx1,
                             const float* __restrict__ bx, const float* __restrict__ bh,
                             const float* __restrict__ bg, const float* __restrict__ wc) {
    int t = blockIdx.x * blockDim.x + threadIdx.x;
    if (t < N_NODES) { g_deg[t] = 0.0f; g_cnt[t] = 0; }
    if (t < 192 * 128) {
        int jp = t >> 7, k = t & 127;
        int f, g3; jmap(jp, f, g3);
        int gg = (g3 == 0) ? 0 : ((g3 == 1) ? 2 : 3);
        float v = (k < 64) ? Wx0[gg * 4096 + k * 64 + f]
                           : Wx1[gg * 4096 + (k - 64) * 64 + f];
        __half h = __float2half_rn(v);
        g_Wh[t] = *reinterpret_cast<unsigned short*>(&h);
    }
    if (t < 192) {
        int f, g3; jmap(t, f, g3);
        int gg = (g3 == 0) ? 0 : ((g3 == 1) ? 2 : 3);
        g_bs[t] = bx[gg * 64 + f] + bh[gg * 64 + f] + bg[gg * 64 + f];
    }
    if (t < 64) g_wo[t] = wc[2 * 64 + t];
}

// X: [N, F, P] fp32 -> g_XH[p][n][pair] fp16
__global__ void transpose_kernel(const float* __restrict__ X) {
    int t = blockIdx.x * blockDim.x + threadIdx.x;
    if (t >= NF / 2) return;
    int n = t >> 5, j = t & 31;
    const float4* src = reinterpret_cast<const float4*>(X + ((size_t)n * 64 + 2 * j) * 8);
    float4 v0 = src[0], v1 = src[1], v2 = src[2], v3 = src[3];
    float f0[8] = {v0.x, v0.y, v0.z, v0.w, v1.x, v1.y, v1.z, v1.w};
    float f1[8] = {v2.x, v2.y, v2.z, v2.w, v3.x, v3.y, v3.z, v3.w};
#pragma unroll
    for (int p = 0; p < PER; p++)
        g_XH[((size_t)p * N_NODES + n) * 32 + j] = packh2(f0[p], f1[p]);
}

__global__ void deg_hist_kernel(const int* __restrict__ ei, const float* __restrict__ ew) {
    int e = blockIdx.x * blockDim.x + threadIdx.x;
    if (e >= E_EDGES) return;
    atomicAdd(&g_deg[ei[e]], ew[e]);
    atomicAdd(&g_cnt[ei[E_EDGES + e]], 1);
}

// single-block scan: stage g_cnt in smem (coalesced), thread-local chunk scan from
// smem (conflict-free: 49 coprime 32), in-place prefix write-back, coalesced copy out.
#define SCAN_SMEM (N_NODES * 4)
__global__ void scan_kernel() {
    extern __shared__ int scnt[];   // 50000 ints = 200KB
    __shared__ int wsum[32];
    const int CH = 49;              // ceil(50000 / 1024)
    int tid = threadIdx.x, lane = tid & 31, wid = tid >> 5;

    // coalesced load g_cnt -> smem (12500 int4)
    for (int i = tid; i < N_NODES / 4; i += 1024)
        ((int4*)scnt)[i] = ((const int4*)g_cnt)[i];
    __syncthreads();

    // thread-local sum over own chunk
    int base = tid * CH;
    int s = 0;
#pragma unroll 7
    for (int i = 0; i < CH; i++) {
        int idx = base + i;
        if (idx < N_NODES) s += scnt[idx];
    }
    // block scan of 1024 partials
    int x = s;
#pragma unroll
    for (int off = 1; off < 32; off <<= 1) {
        int t = __shfl_up_sync(0xffffffffu, x, off);
        if (lane >= off) x += t;
    }
    if (lane == 31) wsum[wid] = x;
    __syncthreads();
    if (wid == 0) {
        int v = wsum[lane];
        int y = v;
#pragma unroll
        for (int off = 1; off < 32; off <<= 1) {
            int t = __shfl_up_sync(0xffffffffu, y, off);
            if (lane >= off) y += t;
        }
        wsum[lane] = y - v;
    }
    __syncthreads();
    // in-place exclusive prefix within own chunk
    int run = (x - s) + wsum[wid];
    int total = (tid == 1023) ? run + s : 0;
#pragma unroll 7
    for (int i = 0; i < CH; i++) {
        int idx = base + i;
        if (idx < N_NODES) {
            int c = scnt[idx];
            scnt[idx] = run;
            run += c;
        }
    }
    __syncthreads();
    // coalesced copy out
    for (int i = tid; i < N_NODES / 4; i += 1024) {
        int4 v = ((const int4*)scnt)[i];
        ((int4*)g_rowptr)[i] = v;
        ((int4*)g_cursor)[i] = v;
    }
    if (tid == 1023) g_rowptr[N_NODES] = total;
}

__global__ void wn_scatter_kernel(const int* __restrict__ ei, const float* __restrict__ ew) {
    int e = blockIdx.x * blockDim.x + threadIdx.x;
    if (e >= E_EDGES) return;
    int s = ei[e], d = ei[E_EDGES + e];
    float ds = g_deg[s], dd = g_deg[d];
    float is = (ds > 0.0f) ? rsqrtf(fmaxf(ds, 1e-12f)) : 0.0f;
    float id = (dd > 0.0f) ? rsqrtf(fmaxf(dd, 1e-12f)) : 0.0f;
    float w = -is * ew[e] * id;
    int pos = atomicAdd(&g_cursor[d], 1);
    g_esrc[pos] = s;
    g_ewn[pos] = w;
}

// ---------------- pull SpMM, ALL periods, fp16 rows (128B gather per row) ----------------
__global__ void __launch_bounds__(256) spmm_all_kernel() {
    int warp = (blockIdx.x * blockDim.x + threadIdx.x) >> 5;
    int lane = threadIdx.x & 31;
    if (warp >= N_NODES) return;
    int beg = g_rowptr[warp], end = g_rowptr[warp + 1];
    float ax[PER], ay[PER];
#pragma unroll
    for (int p = 0; p < PER; p++) { ax[p] = 0.0f; ay[p] = 0.0f; }
    for (int e = beg; e < end; e++) {
        int s = g_esrc[e];
        float w = g_ewn[e];
        const uint32_t* base = g_XH + (size_t)s * 32 + lane;
        uint32_t u[PER];
#pragma unroll
        for (int p = 0; p < PER; p++) u[p] = base[(size_t)p * N_NODES * 32];
#pragma unroll
        for (int p = 0; p < PER; p++) {
            float2 v = __half22float2(*reinterpret_cast<__half2*>(&u[p]));
            ax[p] += w * v.x;
            ay[p] += w * v.y;
        }
    }
#pragma unroll
    for (int p = 0; p < PER; p++)
        g_TH[((size_t)p * N_NODES + warp) * 32 + lane] = packh2(ax[p], ay[p]);
}

// ---------------- fused mma.sync GEMM: all 8 periods per block, 1-pass fp16 ----------------
// smem: A [row 128][k 128] fp16, row stride 272B (256B data); B [jphys 192][k 128] fp16
#define ASTRIDE 272
#define BSTRIDE 272
#define SM_A    0
#define SM_B    34816
#define SMEM_BYTES (34816 + 52224)

__global__ void __launch_bounds__(256, 1) gemm_fused(float* __restrict__ out) {
    extern __shared__ char smem[];
    int tid = threadIdx.x;
    int wid = tid >> 5, lane = tid & 31;
    int g = lane >> 2, tg = lane & 3;
    int wm = wid & 1;          // warp row: 0/1 -> rows 0-63 / 64-127
    int wn = wid >> 1;         // warp col: 0..3 -> jphys base 48*wn
    int r0 = blockIdx.x * 128;

    // ---- B copy (once): [192][128] fp16, 3072 uint4 ----
    for (int it = tid; it < 3072; it += 256) {
        int j = it >> 4, c = it & 15;
        *(uint4*)(smem + SM_B + j * BSTRIDE + c * 16) = ((const uint4*)g_Wh)[j * 16 + c];
    }

    // ---- per-thread biases (thread-local epilogue via column permutation) ----
    float bsv[12], wov[4];
#pragma unroll
    for (int s = 0; s < 12; s++) {
        int nt = s >> 1, e = s & 1;
        bsv[s] = g_bs[wn * 48 + nt * 8 + tg * 2 + e];
    }
#pragma unroll
    for (int t = 0; t < 4; t++) wov[t] = g_wo[wn * 16 + tg * 4 + t];

    float accO[4][2][4];
#pragma unroll
    for (int mt = 0; mt < 4; mt++)
#pragma unroll
        for (int h = 0; h < 2; h++)
#pragma unroll
            for (int t = 0; t < 4; t++) accO[mt][h][t] = 0.0f;

    // copyA pieces: A row = 256B = 16 uint4 (cc<8: X fp16, cc>=8: tx1 fp16)
    int cc = tid & 15, rb = tid >> 4;   // rows rb + 16*i, i<8
    char* dst0 = smem + SM_A + cc * 16;
    int idx4 = (cc < 8) ? cc : (cc - 8);

    // ---- initial A copy (p = 0) ----
    {
        const uint32_t* srcbase = (cc < 8) ? g_XH : g_TH;
#pragma unroll
        for (int i = 0; i < 8; i++) {
            int r = rb + i * 16;
            int gr = r0 + r;
            uint4 u = make_uint4(0, 0, 0, 0);
            if (gr < N_NODES)
                u = ((const uint4*)(srcbase + (size_t)gr * 32))[idx4];
            *(uint4*)(dst0 + r * ASTRIDE) = u;
        }
    }

    for (int p = 0; p < PER; p++) {
        __syncthreads();   // A(p) visible

        // ---- mma: acc[mt][nt][q], single fp16 pass ----
        float acc[4][6][4];
#pragma unroll
        for (int mt = 0; mt < 4; mt++)
#pragma unroll
            for (int nt = 0; nt < 6; nt++)
#pragma unroll
                for (int q = 0; q < 4; q++) acc[mt][nt][q] = 0.0f;

#pragma unroll
        for (int ks = 0; ks < 8; ks++) {
            uint32_t a[4][4];
#pragma unroll
            for (int mt = 0; mt < 4; mt++) {
                const char* ab = smem + SM_A + (wm * 64 + mt * 16 + g) * ASTRIDE
                               + ks * 32 + tg * 4;
                a[mt][0] = *(const uint32_t*)(ab);
                a[mt][1] = *(const uint32_t*)(ab + 8 * ASTRIDE);
                a[mt][2] = *(const uint32_t*)(ab + 16);
                a[mt][3] = *(const uint32_t*)(ab + 8 * ASTRIDE + 16);
            }
#pragma unroll
            for (int nt = 0; nt < 6; nt++) {
                const char* bb = smem + SM_B + (wn * 48 + nt * 8 + g) * BSTRIDE
                               + ks * 32 + tg * 4;
                uint32_t b0 = *(const uint32_t*)(bb);
                uint32_t b1 = *(const uint32_t*)(bb + 16);
#pragma unroll
                for (int mt = 0; mt < 4; mt++)
                    mma_f16(acc[mt][nt], a[mt][0], a[mt][1], a[mt][2], a[mt][3], b0, b1);
            }
        }
        __syncthreads();   // A reads done; safe to overwrite A

        // ---- prefetch A(p+1) into regs, thread-local epilogue, store ----
        bool more = (p + 1 < PER);
        uint4 u[8];
        if (more) {
            const uint32_t* srcbase = ((cc < 8) ? g_XH : g_TH)
                                    + (size_t)(p + 1) * N_NODES * 32;
#pragma unroll
            for (int i = 0; i < 8; i++) {
                int gr = r0 + rb + i * 16;
                u[i] = (gr < N_NODES) ? ((const uint4*)(srcbase + (size_t)gr * 32))[idx4]
                                      : make_uint4(0, 0, 0, 0);
            }
        }
#pragma unroll
        for (int mt = 0; mt < 4; mt++)
#pragma unroll
            for (int h = 0; h < 2; h++)
#pragma unroll
                for (int t = 0; t < 4; t++) {
                    int s0 = 3 * t, s1 = 3 * t + 1, s2 = 3 * t + 2;
                    float gi = acc[mt][s0 >> 1][h * 2 + (s0 & 1)] + bsv[s0];
                    float gc = acc[mt][s1 >> 1][h * 2 + (s1 & 1)] + bsv[s1];
                    float go = acc[mt][s2 >> 1][h * 2 + (s2 & 1)] + bsv[s2];
                    float I  = fsigmoid(gi);
                    float T  = ftanh(gc);
                    float Cn = I * T;
                    float O  = fsigmoid(go + wov[t] * Cn);
                    accO[mt][h][t] += O * ftanh(Cn);
                }
        if (more) {
#pragma unroll
            for (int i = 0; i < 8; i++)
                *(uint4*)(dst0 + (rb + i * 16) * ASTRIDE) = u[i];
        }
    }

    // ---- final output write (write-only, no RMW) ----
#pragma unroll
    for (int mt = 0; mt < 4; mt++)
#pragma unroll
        for (int h = 0; h < 2; h++) {
            int row = r0 + wm * 64 + mt * 16 + g + h * 8;
            if (row < N_NODES) {
                *(float4*)(out + (size_t)row * 64 + wn * 16 + tg * 4) =
                    make_float4(accO[mt][h][0], accO[mt][h][1],
                                accO[mt][h][2], accO[mt][h][3]);
            }
        }
}

// ---------------- launch ----------------
extern "C" void kernel_launch(void* const* d_in, const int* in_sizes, int n_in,
                              void* d_out, int out_size) {
    const float* X   = (const float*)d_in[0];
    const int*   ei  = (const int*)d_in[1];
    const float* ew  = (const float*)d_in[2];
    const float* Wx0 = (const float*)d_in[3];
    const float* Wx1 = (const float*)d_in[4];
    const float* bx  = (const float*)d_in[5];
    // d_in[6]=Wh0, d_in[7]=Wh1 unused (H=0 -> cheb(H)=bh)
    const float* bh  = (const float*)d_in[8];
    const float* wc  = (const float*)d_in[9];
    const float* bg  = (const float*)d_in[10];
    float* out = (float*)d_out;

    cudaFuncSetAttribute(gemm_fused, cudaFuncAttributeMaxDynamicSharedMemorySize, SMEM_BYTES);
    cudaFuncSetAttribute(scan_kernel, cudaFuncAttributeMaxDynamicSharedMemorySize, SCAN_SMEM);

    setup_kernel<<<(N_NODES + 255) / 256, 256>>>(Wx0, Wx1, bx, bh, bg, wc);   // 1
    transpose_kernel<<<(NF / 2 + 255) / 256, 256>>>(X);                        // 2
    deg_hist_kernel<<<(E_EDGES + 255) / 256, 256>>>(ei, ew);                   // 3
    scan_kernel<<<1, 1024, SCAN_SMEM>>>();                                     // 4
    wn_scatter_kernel<<<(E_EDGES + 255) / 256, 256>>>(ei, ew);                 // 5
    spmm_all_kernel<<<(N_NODES * 32 + 255) / 256, 256>>>();                    // 6
    gemm_fused<<<(N_NODES + 127) / 128, 256, SMEM_BYTES>>>(out);               // 7
}

// round 15
// speedup vs baseline: 3.8330x; 1.0546x over previous
#include <cuda_runtime.h>
#include <cuda_fp16.h>
#include <cstdint>

#define N_NODES 50000
#define FDIM    64
#define PER     8
#define E_EDGES 800000
#define NF      (N_NODES * FDIM)

// ---------------- scratch (static __device__ — no allocations) ----------------
__device__ uint32_t g_XH[PER * N_NODES * 32];   // X transposed, fp16 (~51 MB)
__device__ uint32_t g_TH[PER * N_NODES * 32];   // tx1 per period, fp16
__device__ float g_deg[N_NODES];
__device__ __align__(16) int g_cnt[N_NODES];
__device__ int   g_rowptr[N_NODES + 1];
__device__ int   g_cursor[N_NODES];
__device__ int   g_btot[49];
__device__ int   g_esrc[E_EDGES];
__device__ float g_ewn[E_EDGES];
__device__ unsigned short g_Wh[192 * 128];   // W packed [jphys][k], fp16 (permuted cols)
__device__ float g_bs[192];                  // bx+bh+bg, jphys layout
__device__ float g_wo[64];                   // peephole wc[2], logical f

// ---------------- small helpers ----------------
__device__ __forceinline__ float tanh_fast(float x) {
    float r; asm("tanh.approx.f32 %0, %1;" : "=f"(r) : "f"(x)); return r;
}
__device__ __forceinline__ float fsigmoid(float x) {
    return fmaf(tanh_fast(0.5f * x), 0.5f, 0.5f);
}
__device__ __forceinline__ float ftanh(float x) { return tanh_fast(x); }
__device__ __forceinline__ uint32_t packh2(float a, float b) {
    __half2 h = __floats2half2_rn(a, b);
    return *reinterpret_cast<uint32_t*>(&h);
}

// physical B column jphys -> logical (feature f, gate g3 in {0:i,1:c,2:o})
__device__ __forceinline__ void jmap(int jp, int& f, int& g3) {
    int wn = jp / 48, rem = jp % 48;
    int nt = rem >> 3, r8 = rem & 7, tg = r8 >> 1, e = r8 & 1;
    int slot = nt * 2 + e;
    f  = wn * 16 + tg * 4 + slot / 3;
    g3 = slot % 3;
}

__device__ __forceinline__ void mma_f16(float* c,
                                        uint32_t a0, uint32_t a1, uint32_t a2, uint32_t a3,
                                        uint32_t b0, uint32_t b1) {
    asm volatile(
        "mma.sync.aligned.m16n8k16.row.col.f32.f16.f16.f32 "
        "{%0,%1,%2,%3}, {%4,%5,%6,%7}, {%8,%9}, {%0,%1,%2,%3};"
        : "+f"(c[0]), "+f"(c[1]), "+f"(c[2]), "+f"(c[3])
        : "r"(a0), "r"(a1), "r"(a2), "r"(a3), "r"(b0), "r"(b1));
}
__device__ __forceinline__ void ldsm_x4(uint32_t* r, uint32_t addr) {
    asm volatile("ldmatrix.sync.aligned.m8n8.x4.shared.b16 {%0,%1,%2,%3}, [%4];"
        : "=r"(r[0]), "=r"(r[1]), "=r"(r[2]), "=r"(r[3]) : "r"(addr));
}
__device__ __forceinline__ void ldsm_x2(uint32_t& r0, uint32_t& r1, uint32_t addr) {
    asm volatile("ldmatrix.sync.aligned.m8n8.x2.shared.b16 {%0,%1}, [%2];"
        : "=r"(r0), "=r"(r1) : "r"(addr));
}

// ---------------- K1: zero ----------------
__global__ void zero_kernel() {
    int t = blockIdx.x * blockDim.x + threadIdx.x;
    if (t < N_NODES) { g_deg[t] = 0.0f; g_cnt[t] = 0; }
}

// ---------------- K2: degree + dst histogram ----------------
__global__ void deg_hist_kernel(const int* __restrict__ ei, const float* __restrict__ ew) {
    int e = blockIdx.x * blockDim.x + threadIdx.x;
    if (e >= E_EDGES) return;
    atomicAdd(&g_deg[ei[e]], ew[e]);
    atomicAdd(&g_cnt[ei[E_EDGES + e]], 1);
}

// ---------------- K3: block-local scan (49 blocks x 1024) ----------------
__global__ void scan1_kernel() {
    __shared__ int wsum[32];
    int tid = threadIdx.x, lane = tid & 31, wid = tid >> 5;
    int i = blockIdx.x * 1024 + tid;
    int c = (i < N_NODES) ? g_cnt[i] : 0;
    int x = c;
#pragma unroll
    for (int off = 1; off < 32; off <<= 1) {
        int t = __shfl_up_sync(0xffffffffu, x, off);
        if (lane >= off) x += t;
    }
    if (lane == 31) wsum[wid] = x;
    __syncthreads();
    if (wid == 0) {
        int v = wsum[lane];
        int y = v;
#pragma unroll
        for (int off = 1; off < 32; off <<= 1) {
            int t = __shfl_up_sync(0xffffffffu, y, off);
            if (lane >= off) y += t;
        }
        wsum[lane] = y - v;
        if (lane == 31) g_btot[blockIdx.x] = y;
    }
    __syncthreads();
    if (i < N_NODES) g_rowptr[i] = (x - c) + wsum[wid];
}

// ---------------- K4: add block offsets (196 blocks x 256) ----------------
__global__ void scan2_kernel() {
    int bid = blockIdx.x, tid = threadIdx.x;
    int grp = bid >> 2;                 // 4 blocks per 1024-node group
    int off = 0;
    for (int b = 0; b < grp; b++) off += g_btot[b];
    int i = bid * 256 + tid;
    if (i < N_NODES) {
        int v = g_rowptr[i] + off;
        g_rowptr[i] = v;
        g_cursor[i] = v;
    }
    if (bid == 195 && tid == 0) {
        int tot = 0;
        for (int b = 0; b < 49; b++) tot += g_btot[b];
        g_rowptr[N_NODES] = tot;
    }
}

// ---------------- K5: fused scatter (3125) + transpose (6250) + pack (97) ----------------
#define NB_SCAT 3125
#define NB_TRAN 6250
#define NB_PACK 97
__global__ void fused_mid_kernel(const int* __restrict__ ei, const float* __restrict__ ew,
                                 const float* __restrict__ X,
                                 const float* __restrict__ Wx0, const float* __restrict__ Wx1,
                                 const float* __restrict__ bx, const float* __restrict__ bh,
                                 const float* __restrict__ bg, const float* __restrict__ wc) {
    int bid = blockIdx.x, tid = threadIdx.x;
    if (bid < NB_SCAT) {
        // edge scatter into CSR (needs g_deg + g_cursor)
        int e = bid * 256 + tid;
        if (e < E_EDGES) {
            int s = ei[e], d = ei[E_EDGES + e];
            float ds = g_deg[s], dd = g_deg[d];
            float is = (ds > 0.0f) ? rsqrtf(fmaxf(ds, 1e-12f)) : 0.0f;
            float id = (dd > 0.0f) ? rsqrtf(fmaxf(dd, 1e-12f)) : 0.0f;
            float w = -is * ew[e] * id;
            int pos = atomicAdd(&g_cursor[d], 1);
            g_esrc[pos] = s;
            g_ewn[pos] = w;
        }
    } else if (bid < NB_SCAT + NB_TRAN) {
        // X: [N, F, P] fp32 -> g_XH[p][n][pair] fp16
        int t = (bid - NB_SCAT) * 256 + tid;   // t < NF/2 = 1.6M exactly
        int n = t >> 5, j = t & 31;
        const float4* src = reinterpret_cast<const float4*>(X + ((size_t)n * 64 + 2 * j) * 8);
        float4 v0 = src[0], v1 = src[1], v2 = src[2], v3 = src[3];
        float f0[8] = {v0.x, v0.y, v0.z, v0.w, v1.x, v1.y, v1.z, v1.w};
        float f1[8] = {v2.x, v2.y, v2.z, v2.w, v3.x, v3.y, v3.z, v3.w};
#pragma unroll
        for (int p = 0; p < PER; p++)
            g_XH[((size_t)p * N_NODES + n) * 32 + j] = packh2(f0[p], f1[p]);
    } else {
        int pidx = (bid - NB_SCAT - NB_TRAN) * 256 + tid;   // < 24832
        if (pidx < 24576) {
            int jp = pidx >> 7, k = pidx & 127;
            int f, g3; jmap(jp, f, g3);
            int gg = (g3 == 0) ? 0 : ((g3 == 1) ? 2 : 3);   // i, c, o
            float v = (k < 64) ? Wx0[gg * 4096 + k * 64 + f]
                               : Wx1[gg * 4096 + (k - 64) * 64 + f];
            __half h = __float2half_rn(v);
            g_Wh[pidx] = *reinterpret_cast<unsigned short*>(&h);
        } else if (pidx < 24576 + 192) {
            int j = pidx - 24576;
            int f, g3; jmap(j, f, g3);
            int gg = (g3 == 0) ? 0 : ((g3 == 1) ? 2 : 3);
            g_bs[j] = bx[gg * 64 + f] + bh[gg * 64 + f] + bg[gg * 64 + f];
        } else if (pidx < 24576 + 192 + 64) {
            int f = pidx - 24768;
            g_wo[f] = wc[2 * 64 + f];
        }
    }
}

// ---------------- K6: pull SpMM, all periods ----------------
__global__ void __launch_bounds__(256) spmm_all_kernel() {
    int warp = (blockIdx.x * blockDim.x + threadIdx.x) >> 5;
    int lane = threadIdx.x & 31;
    if (warp >= N_NODES) return;
    int beg = g_rowptr[warp], end = g_rowptr[warp + 1];
    float ax[PER], ay[PER];
#pragma unroll
    for (int p = 0; p < PER; p++) { ax[p] = 0.0f; ay[p] = 0.0f; }
    for (int e = beg; e < end; e++) {
        int s = g_esrc[e];
        float w = g_ewn[e];
        const uint32_t* base = g_XH + (size_t)s * 32 + lane;
        uint32_t u[PER];
#pragma unroll
        for (int p = 0; p < PER; p++) u[p] = base[(size_t)p * N_NODES * 32];
#pragma unroll
        for (int p = 0; p < PER; p++) {
            float2 v = __half22float2(*reinterpret_cast<__half2*>(&u[p]));
            ax[p] += w * v.x;
            ay[p] += w * v.y;
        }
    }
#pragma unroll
    for (int p = 0; p < PER; p++)
        g_TH[((size_t)p * N_NODES + warp) * 32 + lane] = packh2(ax[p], ay[p]);
}

// ---------------- K7: fused mma.sync GEMM, ldmatrix fragments ----------------
#define ASTRIDE 272
#define BSTRIDE 272
#define SM_A    0
#define SM_B    34816
#define SMEM_BYTES (34816 + 52224)

__global__ void __launch_bounds__(256, 1) gemm_fused(float* __restrict__ out) {
    extern __shared__ char smem[];
    int tid = threadIdx.x;
    int wid = tid >> 5, lane = tid & 31;
    int g = lane >> 2, tg = lane & 3;
    int wm = wid & 1;          // warp row: 0/1 -> rows 0-63 / 64-127
    int wn = wid >> 1;         // warp col: 0..3 -> jphys base 48*wn
    int r0 = blockIdx.x * 128;

    // ---- B copy (once): [192][128] fp16, 3072 uint4 ----
    for (int it = tid; it < 3072; it += 256) {
        int j = it >> 4, c = it & 15;
        *(uint4*)(smem + SM_B + j * BSTRIDE + c * 16) = ((const uint4*)g_Wh)[j * 16 + c];
    }

    // ---- per-thread biases ----
    float bsv[12], wov[4];
#pragma unroll
    for (int s = 0; s < 12; s++) {
        int nt = s >> 1, e = s & 1;
        bsv[s] = g_bs[wn * 48 + nt * 8 + tg * 2 + e];
    }
#pragma unroll
    for (int t = 0; t < 4; t++) wov[t] = g_wo[wn * 16 + tg * 4 + t];

    float accO[4][2][4];
#pragma unroll
    for (int mt = 0; mt < 4; mt++)
#pragma unroll
        for (int h = 0; h < 2; h++)
#pragma unroll
            for (int t = 0; t < 4; t++) accO[mt][h][t] = 0.0f;

    // ldmatrix per-lane addresses
    uint32_t smA = (uint32_t)__cvta_generic_to_shared(smem + SM_A);
    uint32_t smB = (uint32_t)__cvta_generic_to_shared(smem + SM_B);
    int lrow = lane & 15, khalf = lane >> 4;
    uint32_t aaddr[4];
#pragma unroll
    for (int mt = 0; mt < 4; mt++)
        aaddr[mt] = smA + (wm * 64 + mt * 16 + lrow) * ASTRIDE + khalf * 16;
    int brow = lane & 7, bk = (lane >> 3) & 1;
    uint32_t baddr[6];
#pragma unroll
    for (int nt = 0; nt < 6; nt++)
        baddr[nt] = smB + (wn * 48 + nt * 8 + brow) * BSTRIDE + bk * 16;

    // copyA pieces: A row = 256B = 16 uint4 (cc<8: X fp16, cc>=8: tx1 fp16)
    int cc = tid & 15, rb = tid >> 4;   // rows rb + 16*i, i<8
    char* dst0 = smem + SM_A + cc * 16;
    int idx4 = (cc < 8) ? cc : (cc - 8);

    // ---- initial A copy (p = 0) ----
    {
        const uint32_t* srcbase = (cc < 8) ? g_XH : g_TH;
#pragma unroll
        for (int i = 0; i < 8; i++) {
            int r = rb + i * 16;
            int gr = r0 + r;
            uint4 u = make_uint4(0, 0, 0, 0);
            if (gr < N_NODES)
                u = ((const uint4*)(srcbase + (size_t)gr * 32))[idx4];
            *(uint4*)(dst0 + r * ASTRIDE) = u;
        }
    }

    for (int p = 0; p < PER; p++) {
        __syncthreads();   // A(p) visible

        float acc[4][6][4];
#pragma unroll
        for (int mt = 0; mt < 4; mt++)
#pragma unroll
            for (int nt = 0; nt < 6; nt++)
#pragma unroll
                for (int q = 0; q < 4; q++) acc[mt][nt][q] = 0.0f;

#pragma unroll
        for (int ks = 0; ks < 8; ks++) {
            uint32_t a[4][4];
#pragma unroll
            for (int mt = 0; mt < 4; mt++)
                ldsm_x4(a[mt], aaddr[mt] + ks * 32);
#pragma unroll
            for (int nt = 0; nt < 6; nt++) {
                uint32_t b0, b1;
                ldsm_x2(b0, b1, baddr[nt] + ks * 32);
#pragma unroll
                for (int mt = 0; mt < 4; mt++)
                    mma_f16(acc[mt][nt], a[mt][0], a[mt][1], a[mt][2], a[mt][3], b0, b1);
            }
        }
        __syncthreads();   // A reads done; safe to overwrite A

        // ---- prefetch A(p+1) into regs, thread-local epilogue, store ----
        bool more = (p + 1 < PER);
        uint4 u[8];
        if (more) {
            const uint32_t* srcbase = ((cc < 8) ? g_XH : g_TH)
                                    + (size_t)(p + 1) * N_NODES * 32;
#pragma unroll
            for (int i = 0; i < 8; i++) {
                int gr = r0 + rb + i * 16;
                u[i] = (gr < N_NODES) ? ((const uint4*)(srcbase + (size_t)gr * 32))[idx4]
                                      : make_uint4(0, 0, 0, 0);
            }
        }
#pragma unroll
        for (int mt = 0; mt < 4; mt++)
#pragma unroll
            for (int h = 0; h < 2; h++)
#pragma unroll
                for (int t = 0; t < 4; t++) {
                    int s0 = 3 * t, s1 = 3 * t + 1, s2 = 3 * t + 2;
                    float gi = acc[mt][s0 >> 1][h * 2 + (s0 & 1)] + bsv[s0];
                    float gc = acc[mt][s1 >> 1][h * 2 + (s1 & 1)] + bsv[s1];
                    float go = acc[mt][s2 >> 1][h * 2 + (s2 & 1)] + bsv[s2];
                    float I  = fsigmoid(gi);
                    float T  = ftanh(gc);
                    float Cn = I * T;
                    float O  = fsigmoid(go + wov[t] * Cn);
                    accO[mt][h][t] += O * ftanh(Cn);
                }
        if (more) {
#pragma unroll
            for (int i = 0; i < 8; i++)
                *(uint4*)(dst0 + (rb + i * 16) * ASTRIDE) = u[i];
        }
    }

    // ---- final output write (write-only, no RMW) ----
#pragma unroll
    for (int mt = 0; mt < 4; mt++)
#pragma unroll
        for (int h = 0; h < 2; h++) {
            int row = r0 + wm * 64 + mt * 16 + g + h * 8;
            if (row < N_NODES) {
                *(float4*)(out + (size_t)row * 64 + wn * 16 + tg * 4) =
                    make_float4(accO[mt][h][0], accO[mt][h][1],
                                accO[mt][h][2], accO[mt][h][3]);
            }
        }
}

// ---------------- launch ----------------
extern "C" void kernel_launch(void* const* d_in, const int* in_sizes, int n_in,
                              void* d_out, int out_size) {
    const float* X   = (const float*)d_in[0];
    const int*   ei  = (const int*)d_in[1];
    const float* ew  = (const float*)d_in[2];
    const float* Wx0 = (const float*)d_in[3];
    const float* Wx1 = (const float*)d_in[4];
    const float* bx  = (const float*)d_in[5];
    // d_in[6]=Wh0, d_in[7]=Wh1 unused (H=0 -> cheb(H)=bh)
    const float* bh  = (const float*)d_in[8];
    const float* wc  = (const float*)d_in[9];
    const float* bg  = (const float*)d_in[10];
    float* out = (float*)d_out;

    cudaFuncSetAttribute(gemm_fused, cudaFuncAttributeMaxDynamicSharedMemorySize, SMEM_BYTES);

    zero_kernel<<<(N_NODES + 255) / 256, 256>>>();                             // 1
    deg_hist_kernel<<<(E_EDGES + 255) / 256, 256>>>(ei, ew);                   // 2
    scan1_kernel<<<49, 1024>>>();                                              // 3
    scan2_kernel<<<196, 256>>>();                                              // 4
    fused_mid_kernel<<<NB_SCAT + NB_TRAN + NB_PACK, 256>>>(                    // 5
        ei, ew, X, Wx0, Wx1, bx, bh, bg, wc);
    spmm_all_kernel<<<(N_NODES * 32 + 255) / 256, 256>>>();                    // 6
    gemm_fused<<<(N_NODES + 127) / 128, 256, SMEM_BYTES>>>(out);               // 7
}